// round 9
// baseline (speedup 1.0000x reference)
#include <cuda_runtime.h>
#include <cstdint>

#define NTOK 49
#define CDIM 128
#define NHEAD 4
#define NWIN 64
#define THREADS 512

// ---- persistent prepped buffers (filled by prep kernels each launch) ----
__device__ float g_qkvw[3 * 128 * 132];        // tf32, [j][132] natural k order, q-scale folded
__device__ float g_projw[128 * 132];           // tf32, [j][132]
__device__ float g_qkvb[512];                  // qkv_b (q part scaled) ++ proj_b
__device__ float g_bm[64 * 4 * 49 * 56];       // fused rel-pos-bias + mask, col-padded to 56

// ---- shared memory layout (float offsets) — identical to round 6 ----
#define XS_STR 132
#define XS_OFF 0
#define XS_SZ  (64 * XS_STR)          // 8448
#define R2_OFF (XS_OFF + XS_SZ)       // 8448 : weight tile [128][132] OR attn [4][64][60]
#define R2_SZ  (128 * 132)            // 16896
#define WS_STR 132
#define AT_STR 60
#define AT_HSZ (64 * AT_STR)
#define QKV_OFF (R2_OFF + R2_SZ)      // 25344 : q/k/v [3][4][64][36]
#define QK_STR 36
#define QK_HSZ (64 * QK_STR)
#define QK_CSZ (NHEAD * QK_HSZ)
#define SB_OFF (QKV_OFF + 3 * QK_CSZ) // 52992
#define SMEM_FLOATS (SB_OFF + 512)    // 53504 floats = 214016 bytes

__device__ __forceinline__ float f2tf(float f) {
    uint32_t u;
    asm("cvt.rna.tf32.f32 %0, %1;" : "=r"(u) : "f"(f));
    return __uint_as_float(u);
}
__device__ __forceinline__ uint32_t fau(float f) { return __float_as_uint(f); }

__device__ __forceinline__ void mma8(float c[4], const uint32_t a[4], const uint32_t b[2]) {
    asm volatile(
        "mma.sync.aligned.m16n8k8.row.col.f32.tf32.tf32.f32 "
        "{%0,%1,%2,%3},{%4,%5,%6,%7},{%8,%9},{%0,%1,%2,%3};\n"
        : "+f"(c[0]), "+f"(c[1]), "+f"(c[2]), "+f"(c[3])
        : "r"(a[0]), "r"(a[1]), "r"(a[2]), "r"(a[3]), "r"(b[0]), "r"(b[1]));
}

// ================= prep kernels (once per launch, ~5 us total) =================
__global__ void prep_weights(const float* __restrict__ qkv_w, const float* __restrict__ qkv_b,
                             const float* __restrict__ proj_w, const float* __restrict__ proj_b)
{
    int idx = blockIdx.x * 256 + threadIdx.x;
    const float scale = 0.17677669529663687f;   // 32^-0.5
    if (idx < 49152) {
        int ch = idx >> 14;
        int j  = (idx >> 7) & 127;
        int k  = idx & 127;
        float v = qkv_w[(size_t)(ch * 128 + j) * 128 + k];
        if (ch == 0) v *= scale;
        g_qkvw[ch * 16896 + j * 132 + k] = f2tf(v);
    } else if (idx < 65536) {
        int i2 = idx - 49152;
        int j = i2 >> 7, k = i2 & 127;
        g_projw[j * 132 + k] = f2tf(proj_w[(size_t)j * 128 + k]);
    } else if (idx < 65536 + 384) {
        int i = idx - 65536;
        float v = qkv_b[i];
        if (i < 128) v *= scale;
        g_qkvb[i] = v;
    } else if (idx < 65536 + 512) {
        int i = idx - 65536;
        g_qkvb[i] = proj_b[i - 384];
    }
}

__global__ void prep_bm(const float* __restrict__ mask, const float* __restrict__ bias_table)
{
    int idx = blockIdx.x * 256 + threadIdx.x;
    if (idx >= 64 * 4 * 49 * 56) return;
    int j = idx % 56;
    int rest = idx / 56;
    int i = rest % 49; rest /= 49;
    int h = rest & 3;
    int w = rest >> 2;
    float v = 0.f;
    if (j < 49) {
        int ih = i / 7, iw = i - 7 * ih;
        int jh = j / 7, jw = j - 7 * jh;
        int ridx = (ih - jh + 6) * 13 + (iw - jw + 6);
        v = bias_table[ridx * 4 + h] + mask[(size_t)(w * 49 + i) * 49 + j];
    }
    g_bm[idx] = v;
}

// ================= main kernel =================
__global__ __launch_bounds__(THREADS, 1)
void window_attn_tc(const float* __restrict__ x, float* __restrict__ out)
{
    extern __shared__ float s[];
    float* xs = s + XS_OFF;           // [64][132] tf32: x tile, later attn-out tile
    float* r2 = s + R2_OFF;           // weight tile or attn scores
    float* sb = s + SB_OFF;           // biases

    const int tid  = threadIdx.x;
    const int wid  = tid >> 5;
    const int lane = tid & 31;
    const int g    = lane >> 2;
    const int t    = lane & 3;
    const int b    = blockIdx.x;

    // ---- Phase 1: load x tile (tf32), zero-pad rows 49..63 ; stage biases ----
    {
        const float4* xb = (const float4*)(x + (size_t)b * (NTOK * CDIM));
        for (int i = tid; i < 64 * 32; i += THREADS) {
            int r = i >> 5, c4 = i & 31;
            float4 v = (r < NTOK) ? xb[r * 32 + c4] : make_float4(0.f, 0.f, 0.f, 0.f);
            float* d = xs + r * XS_STR + c4 * 4;
            d[0] = f2tf(v.x); d[1] = f2tf(v.y); d[2] = f2tf(v.z); d[3] = f2tf(v.w);
        }
        sb[tid] = g_qkvb[tid];        // THREADS == 512 == bias count
    }
    __syncthreads();

    // ---- Phase 2: QKV = x @ qkv_w^T + b, 3 chunks; 8 warps x (32x32) tiles ----
    for (int ch = 0; ch < 3; ch++) {
        {
            const float4* src = (const float4*)(g_qkvw + ch * 16896);
            float4* dst = (float4*)r2;
            for (int i = tid; i < 4224; i += THREADS) dst[i] = src[i];
        }
        __syncthreads();

        if (wid < 8) {
            const int mi2 = wid & 1;      // 32-row block
            const int nq  = wid >> 1;     // 32-col block
            const int rA  = mi2 * 32 + g;

            float acc[2][4][4];
#pragma unroll
            for (int u = 0; u < 2; u++)
#pragma unroll
                for (int i = 0; i < 4; i++)
#pragma unroll
                    for (int j = 0; j < 4; j++) acc[u][i][j] = 0.f;

#pragma unroll
            for (int ks = 0; ks < 16; ks++) {
                const int k0 = ks * 8;
                const float* ar0 = xs + rA * XS_STR + k0 + t;
                const float* ar1 = ar0 + 16 * XS_STR;
                uint32_t a0[4] = { fau(ar0[0]), fau(ar0[8 * XS_STR]),
                                   fau(ar0[4]), fau(ar0[8 * XS_STR + 4]) };
                uint32_t a1[4] = { fau(ar1[0]), fau(ar1[8 * XS_STR]),
                                   fau(ar1[4]), fau(ar1[8 * XS_STR + 4]) };
#pragma unroll
                for (int nt = 0; nt < 4; nt++) {
                    const float* br = r2 + (nq * 32 + nt * 8 + g) * WS_STR + k0 + t;
                    uint32_t bb[2] = { fau(br[0]), fau(br[4]) };
                    mma8(acc[0][nt], a0, bb);
                    mma8(acc[1][nt], a1, bb);
                }
            }

            // epilogue -> q/k/v smem (tf32); bias from smem
            float* dst = s + QKV_OFF + ch * QK_CSZ;
            const float* bch = sb + ch * 128;
#pragma unroll
            for (int u = 0; u < 2; u++) {
                const int r0 = rA + u * 16;
#pragma unroll
                for (int nt = 0; nt < 4; nt++) {
                    const int c0 = nq * 32 + nt * 8 + 2 * t;
#pragma unroll
                    for (int e = 0; e < 4; e++) {
                        const int rr = r0 + ((e >= 2) ? 8 : 0);
                        const int cc = c0 + (e & 1);
                        const int h = cc >> 5, dd = cc & 31;
                        dst[h * QK_HSZ + rr * QK_STR + dd] = f2tf(acc[u][nt][e] + bch[cc]);
                    }
                }
            }
        }
        __syncthreads();
    }

    // ---- Phase 3: scores = q k^T + fused(bias+mask) -> attn [4][64][60] ----
    {
        const int h  = wid >> 2;
        const int mi = wid & 3;
        const int r0 = mi * 16 + g;
        const float* qh = s + QKV_OFF + 0 * QK_CSZ + h * QK_HSZ;
        const float* kh = s + QKV_OFF + 1 * QK_CSZ + h * QK_HSZ;

        float acc[7][4];
#pragma unroll
        for (int i = 0; i < 7; i++)
#pragma unroll
            for (int j = 0; j < 4; j++) acc[i][j] = 0.f;

#pragma unroll
        for (int ks = 0; ks < 4; ks++) {
            const int k0 = ks * 8;
            const float* ar = qh + r0 * QK_STR + k0 + t;
            uint32_t a[4] = { fau(ar[0]), fau(ar[8 * QK_STR]),
                              fau(ar[4]), fau(ar[8 * QK_STR + 4]) };
#pragma unroll
            for (int nt = 0; nt < 7; nt++) {
                const float* br = kh + (nt * 8 + g) * QK_STR + k0 + t;
                uint32_t bb[2] = { fau(br[0]), fau(br[4]) };
                mma8(acc[nt], a, bb);
            }
        }

        float* at = r2 + h * AT_HSZ;
        const float* bmw = g_bm + (size_t)(b & (NWIN - 1)) * (4 * 49 * 56) + h * (49 * 56);
        const int rA = r0, rB = r0 + 8;
#pragma unroll
        for (int nt = 0; nt < 7; nt++) {
            const int c0 = nt * 8 + 2 * t;
#pragma unroll
            for (int e = 0; e < 4; e++) {
                const int rr = (e >= 2) ? rB : rA;
                const int jj = c0 + (e & 1);
                float v = 0.f;
                if (rr < NTOK && jj < NTOK)
                    v = acc[nt][e] + __ldg(bmw + rr * 56 + jj);
                at[rr * AT_STR + jj] = v;
            }
        }
    }
    __syncthreads();

    // ---- Phase 4: softmax per (h, i<49) row ----
    if (tid < NHEAD * NTOK) {
        const int h = tid / NTOK;
        const int i = tid - h * NTOK;
        float* row = r2 + h * AT_HSZ + i * AT_STR;
        float m = row[0];
#pragma unroll
        for (int j = 1; j < NTOK; j++) m = fmaxf(m, row[j]);
        float ssum = 0.f;
#pragma unroll
        for (int j = 0; j < NTOK; j++) ssum += __expf(row[j] - m);
        const float inv = 1.0f / ssum;
#pragma unroll
        for (int j = 0; j < NTOK; j++) row[j] = f2tf(__expf(row[j] - m) * inv);
    }
    __syncthreads();

    // ---- Phase 5: o = attn @ v -> xs [64][132] (cols h*32+d), tf32 ----
    {
        const int h  = wid >> 2;
        const int mi = wid & 3;
        const int r0 = mi * 16 + g;
        const float* at = r2 + h * AT_HSZ;
        const float* vh = s + QKV_OFF + 2 * QK_CSZ + h * QK_HSZ;

        float acc[4][4];
#pragma unroll
        for (int i = 0; i < 4; i++)
#pragma unroll
            for (int j = 0; j < 4; j++) acc[i][j] = 0.f;

#pragma unroll
        for (int ks = 0; ks < 7; ks++) {
            const int k0 = ks * 8;
            const float* ar = at + r0 * AT_STR + k0 + t;
            uint32_t a[4] = { fau(ar[0]), fau(ar[8 * AT_STR]),
                              fau(ar[4]), fau(ar[8 * AT_STR + 4]) };
#pragma unroll
            for (int nt = 0; nt < 4; nt++) {
                const float* br = vh + (k0 + t) * QK_STR + nt * 8 + g;
                uint32_t bb[2] = { fau(br[0]), fau(br[4 * QK_STR]) };
                mma8(acc[nt], a, bb);
            }
        }
        __syncthreads();   // attn reads done before r2 is overwritten with proj_w

#pragma unroll
        for (int nt = 0; nt < 4; nt++) {
            const int c0 = nt * 8 + 2 * t;
#pragma unroll
            for (int e = 0; e < 4; e++) {
                const int rr = r0 + ((e >= 2) ? 8 : 0);
                const int dd = c0 + (e & 1);
                xs[rr * XS_STR + h * 32 + dd] = f2tf(acc[nt][e]);
            }
        }
    }
    __syncthreads();

    // ---- Phase 6: final = o @ proj_w^T + proj_b ; 8 warps x (32x32) tiles ----
    {
        const float4* src = (const float4*)g_projw;
        float4* dst = (float4*)r2;
        for (int i = tid; i < 4224; i += THREADS) dst[i] = src[i];
    }
    __syncthreads();
    if (wid < 8) {
        const int mi2 = wid & 1;
        const int nq  = wid >> 1;
        const int rA  = mi2 * 32 + g;

        float acc[2][4][4];
#pragma unroll
        for (int u = 0; u < 2; u++)
#pragma unroll
            for (int i = 0; i < 4; i++)
#pragma unroll
                for (int j = 0; j < 4; j++) acc[u][i][j] = 0.f;

#pragma unroll
        for (int ks = 0; ks < 16; ks++) {
            const int k0 = ks * 8;
            const float* ar0 = xs + rA * XS_STR + k0 + t;
            const float* ar1 = ar0 + 16 * XS_STR;
            uint32_t a0[4] = { fau(ar0[0]), fau(ar0[8 * XS_STR]),
                               fau(ar0[4]), fau(ar0[8 * XS_STR + 4]) };
            uint32_t a1[4] = { fau(ar1[0]), fau(ar1[8 * XS_STR]),
                               fau(ar1[4]), fau(ar1[8 * XS_STR + 4]) };
#pragma unroll
            for (int nt = 0; nt < 4; nt++) {
                const float* br = r2 + (nq * 32 + nt * 8 + g) * WS_STR + k0 + t;
                uint32_t bb[2] = { fau(br[0]), fau(br[4]) };
                mma8(acc[0][nt], a0, bb);
                mma8(acc[1][nt], a1, bb);
            }
        }

        // stage into smem (QKV region, free now) for coalesced global store
        float* os = s + QKV_OFF;      // [64][132]
#pragma unroll
        for (int u = 0; u < 2; u++) {
            const int r0 = rA + u * 16;
#pragma unroll
            for (int nt = 0; nt < 4; nt++) {
                const int c0 = nq * 32 + nt * 8 + 2 * t;
#pragma unroll
                for (int e = 0; e < 4; e++) {
                    const int rr = r0 + ((e >= 2) ? 8 : 0);
                    const int cc = c0 + (e & 1);
                    os[rr * XS_STR + cc] = acc[u][nt][e] + sb[384 + cc];
                }
            }
        }
    }
    __syncthreads();
    {
        float* os = s + QKV_OFF;
        float4* ob = (float4*)(out + (size_t)b * (NTOK * CDIM));
        for (int i = tid; i < NTOK * 32; i += THREADS) {
            int r = i >> 5, c4 = i & 31;
            const float* p = os + r * XS_STR + c4 * 4;
            ob[i] = make_float4(p[0], p[1], p[2], p[3]);
        }
    }
}

extern "C" void kernel_launch(void* const* d_in, const int* in_sizes, int n_in,
                              void* d_out, int out_size)
{
    const float* x          = (const float*)d_in[0];
    const float* mask       = (const float*)d_in[1];
    const float* qkv_w      = (const float*)d_in[2];
    const float* qkv_b      = (const float*)d_in[3];
    const float* proj_w     = (const float*)d_in[4];
    const float* proj_b     = (const float*)d_in[5];
    const float* bias_table = (const float*)d_in[6];
    float* out = (float*)d_out;

    const int B = in_sizes[0] / (NTOK * CDIM);   // 8192
    const int smem_bytes = SMEM_FLOATS * (int)sizeof(float);

    prep_weights<<<(66048 + 255) / 256, 256>>>(qkv_w, qkv_b, proj_w, proj_b);
    prep_bm<<<(64 * 4 * 49 * 56 + 255) / 256, 256>>>(mask, bias_table);

    cudaFuncSetAttribute(window_attn_tc,
                         cudaFuncAttributeMaxDynamicSharedMemorySize, smem_bytes);

    window_attn_tc<<<B, THREADS, smem_bytes>>>(x, out);
}

// round 10
// speedup vs baseline: 1.1112x; 1.1112x over previous
#include <cuda_runtime.h>
#include <cstdint>

#define NTOK 49
#define CDIM 128
#define NHEAD 4
#define NWIN 64
#define THREADS 512

// ---- persistent prepped buffers (filled by prep kernel each launch) ----
__device__ __align__(16) float g_qkvw[3 * 128 * 132];  // tf32, [j][132], q-scale folded
__device__ __align__(16) float g_projw[128 * 132];     // tf32, [j][132]
__device__ float g_qkvb[512];                          // qkv_b (q part scaled) ++ proj_b
__device__ float g_bm[64 * 4 * 49 * 56];               // fused rel-pos-bias + mask

// ---- shared memory layout (float offsets) ----
#define XS_STR 132
#define XS_OFF 0
#define XS_SZ  (64 * XS_STR)            // 8448
#define R2_OFF (XS_OFF + XS_SZ)         // 8448 : 2 weight half-buffers [128][68] OR attn [4][64][60]
#define WB_STR 68
#define WB_HALF (128 * WB_STR)          // 8704
#define R2_SZ  (2 * WB_HALF)            // 17408 (attn needs 15360, fits)
#define AT_STR 60
#define AT_HSZ (64 * AT_STR)
#define QKV_OFF (R2_OFF + R2_SZ)        // 25856 : q/k/v [3][4][64][36]
#define QK_STR 36
#define QK_HSZ (64 * QK_STR)
#define QK_CSZ (NHEAD * QK_HSZ)
#define SB_OFF (QKV_OFF + 3 * QK_CSZ)   // 53504
#define SMEM_FLOATS (SB_OFF + 512)      // 54016 floats = 216064 bytes

__device__ __forceinline__ float f2tf(float f) {
    uint32_t u;
    asm("cvt.rna.tf32.f32 %0, %1;" : "=r"(u) : "f"(f));
    return __uint_as_float(u);
}
__device__ __forceinline__ uint32_t fau(float f) { return __float_as_uint(f); }

__device__ __forceinline__ void mma8(float c[4], const uint32_t a[4], const uint32_t b[2]) {
    asm volatile(
        "mma.sync.aligned.m16n8k8.row.col.f32.tf32.tf32.f32 "
        "{%0,%1,%2,%3},{%4,%5,%6,%7},{%8,%9},{%0,%1,%2,%3};\n"
        : "+f"(c[0]), "+f"(c[1]), "+f"(c[2]), "+f"(c[3])
        : "r"(a[0]), "r"(a[1]), "r"(a[2]), "r"(a[3]), "r"(b[0]), "r"(b[1]));
}

__device__ __forceinline__ uint32_t smem_u32(const void* p) {
    return (uint32_t)__cvta_generic_to_shared(p);
}
__device__ __forceinline__ void cp16(uint32_t dst, const void* src) {
    asm volatile("cp.async.cg.shared.global [%0], [%1], 16;\n" :: "r"(dst), "l"(src) : "memory");
}
#define CP_COMMIT asm volatile("cp.async.commit_group;\n" ::: "memory")
#define CP_WAIT0  asm volatile("cp.async.wait_group 0;\n" ::: "memory")
#define CP_WAIT1  asm volatile("cp.async.wait_group 1;\n" ::: "memory")

// stage one k-half (64 cols) of a [128][132] weight matrix into [128][68] buffer
__device__ __forceinline__ void stage_half(float* buf, const float* gsrc, int hf, int tid) {
#pragma unroll
    for (int i = 0; i < 4; i++) {
        int idx = tid + i * THREADS;          // 0..2047
        int row = idx >> 4, c4 = idx & 15;
        cp16(smem_u32(buf + row * WB_STR + c4 * 4),
             gsrc + row * 132 + hf * 64 + c4 * 4);
    }
}

// ================= merged prep kernel (once per launch) =================
#define BM_N (64 * 4 * 49 * 56)
__global__ void prep_all(const float* __restrict__ qkv_w, const float* __restrict__ qkv_b,
                         const float* __restrict__ proj_w, const float* __restrict__ proj_b,
                         const float* __restrict__ mask, const float* __restrict__ bias_table)
{
    int idx = blockIdx.x * 256 + threadIdx.x;
    const float scale = 0.17677669529663687f;   // 32^-0.5
    if (idx < BM_N) {
        int j = idx % 56;
        int rest = idx / 56;
        int i = rest % 49; rest /= 49;
        int h = rest & 3;
        int w = rest >> 2;
        float v = 0.f;
        if (j < 49) {
            int ih = i / 7, iw = i - 7 * ih;
            int jh = j / 7, jw = j - 7 * jh;
            int ridx = (ih - jh + 6) * 13 + (iw - jw + 6);
            v = bias_table[ridx * 4 + h] + mask[(size_t)(w * 49 + i) * 49 + j];
        }
        g_bm[idx] = v;
        return;
    }
    idx -= BM_N;
    if (idx < 49152) {
        int ch = idx >> 14;
        int j  = (idx >> 7) & 127;
        int k  = idx & 127;
        float v = qkv_w[(size_t)(ch * 128 + j) * 128 + k];
        if (ch == 0) v *= scale;
        g_qkvw[ch * 16896 + j * 132 + k] = f2tf(v);
    } else if (idx < 65536) {
        int i2 = idx - 49152;
        int j = i2 >> 7, k = i2 & 127;
        g_projw[j * 132 + k] = f2tf(proj_w[(size_t)j * 128 + k]);
    } else if (idx < 65536 + 384) {
        int i = idx - 65536;
        float v = qkv_b[i];
        if (i < 128) v *= scale;
        g_qkvb[i] = v;
    } else if (idx < 65536 + 512) {
        int i = idx - 65536;
        g_qkvb[i] = proj_b[i - 384];
    }
}

// ================= main kernel =================
__global__ __launch_bounds__(THREADS, 1)
void wattn(const float* __restrict__ x, float* __restrict__ out)
{
    extern __shared__ float s[];
    float* xs   = s + XS_OFF;          // [64][132] tf32: x tile, later o tile
    float* buf0 = s + R2_OFF;          // weight half-buffers / attn scores
    float* buf1 = s + R2_OFF + WB_HALF;
    float* at0  = s + R2_OFF;          // attn region alias
    float* sb   = s + SB_OFF;

    const int tid  = threadIdx.x;
    const int wid  = tid >> 5;
    const int lane = tid & 31;
    const int g    = lane >> 2;
    const int t    = lane & 3;
    const int b    = blockIdx.x;

    // ---- prefetch chunk-0 weights (both halves) before anything else ----
    stage_half(buf0, g_qkvw, 0, tid); CP_COMMIT;
    stage_half(buf1, g_qkvw, 1, tid); CP_COMMIT;

    // ---- Phase 1: x -> tf32 tile [64][132], zero-pad rows 49..63; biases ----
    {
        const float4* xb = (const float4*)(x + (size_t)b * (NTOK * CDIM));
        for (int i = tid; i < 64 * 32; i += THREADS) {
            int r = i >> 5, c4 = i & 31;
            float4 v = (r < NTOK) ? xb[r * 32 + c4] : make_float4(0.f, 0.f, 0.f, 0.f);
            float* d = xs + r * XS_STR + c4 * 4;
            d[0] = f2tf(v.x); d[1] = f2tf(v.y); d[2] = f2tf(v.z); d[3] = f2tf(v.w);
        }
        sb[tid] = g_qkvb[tid];
    }

    // ---- Phase 2: QKV GEMM, 3 chunks, cp.async double-buffered k-halves ----
    for (int ch = 0; ch < 3; ch++) {
        CP_WAIT1;                 // half0 of this chunk loaded (own groups)
        __syncthreads();          // + xs/sb visible (first iter), all threads' copies done

        float acc[2][4][4];
        const int mi2 = wid & 1;
        const int nq  = wid >> 1;
        const int rA  = mi2 * 32 + g;
        if (wid < 8) {
#pragma unroll
            for (int u = 0; u < 2; u++)
#pragma unroll
                for (int i = 0; i < 4; i++)
#pragma unroll
                    for (int j = 0; j < 4; j++) acc[u][i][j] = 0.f;

            // half 0 : k = 0..63
#pragma unroll
            for (int ks = 0; ks < 8; ks++) {
                const int k0 = ks * 8;
                const float* ar0 = xs + rA * XS_STR + k0 + t;
                const float* ar1 = ar0 + 16 * XS_STR;
                uint32_t a0[4] = { fau(ar0[0]), fau(ar0[8 * XS_STR]),
                                   fau(ar0[4]), fau(ar0[8 * XS_STR + 4]) };
                uint32_t a1[4] = { fau(ar1[0]), fau(ar1[8 * XS_STR]),
                                   fau(ar1[4]), fau(ar1[8 * XS_STR + 4]) };
#pragma unroll
                for (int nt = 0; nt < 4; nt++) {
                    const float* br = buf0 + (nq * 32 + nt * 8 + g) * WB_STR + k0 + t;
                    uint32_t bb[2] = { fau(br[0]), fau(br[4]) };
                    mma8(acc[0][nt], a0, bb);
                    mma8(acc[1][nt], a1, bb);
                }
            }
        }
        __syncthreads();          // all reads of buf0 done
        if (ch < 2) { stage_half(buf0, g_qkvw + (ch + 1) * 16896, 0, tid); CP_COMMIT; }

        if (ch < 2) { CP_WAIT1; } else { CP_WAIT0; }   // half1 of this chunk loaded
        __syncthreads();

        if (wid < 8) {
            // half 1 : k = 64..127
#pragma unroll
            for (int ks = 0; ks < 8; ks++) {
                const int k0 = ks * 8;
                const float* ar0 = xs + rA * XS_STR + 64 + k0 + t;
                const float* ar1 = ar0 + 16 * XS_STR;
                uint32_t a0[4] = { fau(ar0[0]), fau(ar0[8 * XS_STR]),
                                   fau(ar0[4]), fau(ar0[8 * XS_STR + 4]) };
                uint32_t a1[4] = { fau(ar1[0]), fau(ar1[8 * XS_STR]),
                                   fau(ar1[4]), fau(ar1[8 * XS_STR + 4]) };
#pragma unroll
                for (int nt = 0; nt < 4; nt++) {
                    const float* br = buf1 + (nq * 32 + nt * 8 + g) * WB_STR + k0 + t;
                    uint32_t bb[2] = { fau(br[0]), fau(br[4]) };
                    mma8(acc[0][nt], a0, bb);
                    mma8(acc[1][nt], a1, bb);
                }
            }

            // epilogue -> q/k/v smem (tf32)
            float* dst = s + QKV_OFF + ch * QK_CSZ;
            const float* bch = sb + ch * 128;
#pragma unroll
            for (int u = 0; u < 2; u++) {
                const int r0 = rA + u * 16;
#pragma unroll
                for (int nt = 0; nt < 4; nt++) {
                    const int c0 = nq * 32 + nt * 8 + 2 * t;
#pragma unroll
                    for (int e = 0; e < 4; e++) {
                        const int rr = r0 + ((e >= 2) ? 8 : 0);
                        const int cc = c0 + (e & 1);
                        const int h = cc >> 5, dd = cc & 31;
                        dst[h * QK_HSZ + rr * QK_STR + dd] = f2tf(acc[u][nt][e] + bch[cc]);
                    }
                }
            }
        }
        __syncthreads();          // buf1 reads done + epilogue visible
        if (ch < 2) { stage_half(buf1, g_qkvw + (ch + 1) * 16896, 1, tid); CP_COMMIT; }
    }

    // ---- Phase 3: scores = q k^T + fused(bias+mask) -> attn [4][64][60] ----
    {
        const int h  = wid >> 2;
        const int mi = wid & 3;
        const int r0 = mi * 16 + g;
        const float* qh = s + QKV_OFF + 0 * QK_CSZ + h * QK_HSZ;
        const float* kh = s + QKV_OFF + 1 * QK_CSZ + h * QK_HSZ;

        float acc[7][4];
#pragma unroll
        for (int i = 0; i < 7; i++)
#pragma unroll
            for (int j = 0; j < 4; j++) acc[i][j] = 0.f;

#pragma unroll
        for (int ks = 0; ks < 4; ks++) {
            const int k0 = ks * 8;
            const float* ar = qh + r0 * QK_STR + k0 + t;
            uint32_t a[4] = { fau(ar[0]), fau(ar[8 * QK_STR]),
                              fau(ar[4]), fau(ar[8 * QK_STR + 4]) };
#pragma unroll
            for (int nt = 0; nt < 7; nt++) {
                const float* br = kh + (nt * 8 + g) * QK_STR + k0 + t;
                uint32_t bb[2] = { fau(br[0]), fau(br[4]) };
                mma8(acc[nt], a, bb);
            }
        }

        float* at = at0 + h * AT_HSZ;
        const float* bmw = g_bm + (size_t)(b & (NWIN - 1)) * (4 * 49 * 56) + h * (49 * 56);
        const int rA = r0, rB = r0 + 8;
#pragma unroll
        for (int nt = 0; nt < 7; nt++) {
            const int c0 = nt * 8 + 2 * t;
#pragma unroll
            for (int e = 0; e < 4; e++) {
                const int rr = (e >= 2) ? rB : rA;
                const int jj = c0 + (e & 1);
                float v = 0.f;
                if (rr < NTOK && jj < NTOK)
                    v = acc[nt][e] + __ldg(bmw + rr * 56 + jj);
                at[rr * AT_STR + jj] = v;
            }
        }
    }
    __syncthreads();

    // ---- Phase 4: softmax per (h, i<49) row ----
    if (tid < NHEAD * NTOK) {
        const int h = tid / NTOK;
        const int i = tid - h * NTOK;
        float* row = at0 + h * AT_HSZ + i * AT_STR;
        float m = row[0];
#pragma unroll
        for (int j = 1; j < NTOK; j++) m = fmaxf(m, row[j]);
        float ssum = 0.f;
#pragma unroll
        for (int j = 0; j < NTOK; j++) ssum += __expf(row[j] - m);
        const float inv = 1.0f / ssum;
#pragma unroll
        for (int j = 0; j < NTOK; j++) row[j] = f2tf(__expf(row[j] - m) * inv);
    }
    __syncthreads();

    // ---- Phase 5: o = attn @ v ; prefetch proj weights; o -> xs ----
    {
        const int h  = wid >> 2;
        const int mi = wid & 3;
        const int r0 = mi * 16 + g;
        const float* at = at0 + h * AT_HSZ;
        const float* vh = s + QKV_OFF + 2 * QK_CSZ + h * QK_HSZ;

        float acc[4][4];
#pragma unroll
        for (int i = 0; i < 4; i++)
#pragma unroll
            for (int j = 0; j < 4; j++) acc[i][j] = 0.f;

#pragma unroll
        for (int ks = 0; ks < 7; ks++) {
            const int k0 = ks * 8;
            const float* ar = at + r0 * AT_STR + k0 + t;
            uint32_t a[4] = { fau(ar[0]), fau(ar[8 * AT_STR]),
                              fau(ar[4]), fau(ar[8 * AT_STR + 4]) };
#pragma unroll
            for (int nt = 0; nt < 4; nt++) {
                const float* br = vh + (k0 + t) * QK_STR + nt * 8 + g;
                uint32_t bb[2] = { fau(br[0]), fau(br[4 * QK_STR]) };
                mma8(acc[nt], a, bb);
            }
        }
        __syncthreads();   // all attn reads done -> r2 region free for proj prefetch

        stage_half(buf0, g_projw, 0, tid); CP_COMMIT;
        stage_half(buf1, g_projw, 1, tid); CP_COMMIT;

#pragma unroll
        for (int nt = 0; nt < 4; nt++) {
            const int c0 = nt * 8 + 2 * t;
#pragma unroll
            for (int e = 0; e < 4; e++) {
                const int rr = r0 + ((e >= 2) ? 8 : 0);
                const int dd = c0 + (e & 1);
                xs[rr * XS_STR + h * 32 + dd] = f2tf(acc[nt][e]);
            }
        }
    }
    CP_WAIT1;
    __syncthreads();       // xs(o) visible + proj half0 loaded everywhere

    // ---- Phase 6: final = o @ proj_w^T + proj_b ; 8 warps x (32x32) tiles ----
    {
        float acc[2][4][4];
        const int mi2 = wid & 1;
        const int nq  = wid >> 1;
        const int rA  = mi2 * 32 + g;
        if (wid < 8) {
#pragma unroll
            for (int u = 0; u < 2; u++)
#pragma unroll
                for (int i = 0; i < 4; i++)
#pragma unroll
                    for (int j = 0; j < 4; j++) acc[u][i][j] = 0.f;

#pragma unroll
            for (int ks = 0; ks < 8; ks++) {
                const int k0 = ks * 8;
                const float* ar0 = xs + rA * XS_STR + k0 + t;
                const float* ar1 = ar0 + 16 * XS_STR;
                uint32_t a0[4] = { fau(ar0[0]), fau(ar0[8 * XS_STR]),
                                   fau(ar0[4]), fau(ar0[8 * XS_STR + 4]) };
                uint32_t a1[4] = { fau(ar1[0]), fau(ar1[8 * XS_STR]),
                                   fau(ar1[4]), fau(ar1[8 * XS_STR + 4]) };
#pragma unroll
                for (int nt = 0; nt < 4; nt++) {
                    const float* br = buf0 + (nq * 32 + nt * 8 + g) * WB_STR + k0 + t;
                    uint32_t bb[2] = { fau(br[0]), fau(br[4]) };
                    mma8(acc[0][nt], a0, bb);
                    mma8(acc[1][nt], a1, bb);
                }
            }
        }
        CP_WAIT0;
        __syncthreads();    // proj half1 loaded everywhere (buf0 not rewritten)

        if (wid < 8) {
#pragma unroll
            for (int ks = 0; ks < 8; ks++) {
                const int k0 = ks * 8;
                const float* ar0 = xs + rA * XS_STR + 64 + k0 + t;
                const float* ar1 = ar0 + 16 * XS_STR;
                uint32_t a0[4] = { fau(ar0[0]), fau(ar0[8 * XS_STR]),
                                   fau(ar0[4]), fau(ar0[8 * XS_STR + 4]) };
                uint32_t a1[4] = { fau(ar1[0]), fau(ar1[8 * XS_STR]),
                                   fau(ar1[4]), fau(ar1[8 * XS_STR + 4]) };
#pragma unroll
                for (int nt = 0; nt < 4; nt++) {
                    const float* br = buf1 + (nq * 32 + nt * 8 + g) * WB_STR + k0 + t;
                    uint32_t bb[2] = { fau(br[0]), fau(br[4]) };
                    mma8(acc[0][nt], a0, bb);
                    mma8(acc[1][nt], a1, bb);
                }
            }

            // stage into qkv region (free now) for coalesced store
            float* os = s + QKV_OFF;      // [64][132]
#pragma unroll
            for (int u = 0; u < 2; u++) {
                const int r0 = rA + u * 16;
#pragma unroll
                for (int nt = 0; nt < 4; nt++) {
                    const int c0 = nq * 32 + nt * 8 + 2 * t;
#pragma unroll
                    for (int e = 0; e < 4; e++) {
                        const int rr = r0 + ((e >= 2) ? 8 : 0);
                        const int cc = c0 + (e & 1);
                        os[rr * XS_STR + cc] = acc[u][nt][e] + sb[384 + cc];
                    }
                }
            }
        }
    }
    __syncthreads();
    {
        float* os = s + QKV_OFF;
        float4* ob = (float4*)(out + (size_t)b * (NTOK * CDIM));
        for (int i = tid; i < NTOK * 32; i += THREADS) {
            int r = i >> 5, c4 = i & 31;
            const float* p = os + r * XS_STR + c4 * 4;
            ob[i] = make_float4(p[0], p[1], p[2], p[3]);
        }
    }
}

extern "C" void kernel_launch(void* const* d_in, const int* in_sizes, int n_in,
                              void* d_out, int out_size)
{
    const float* x          = (const float*)d_in[0];
    const float* mask       = (const float*)d_in[1];
    const float* qkv_w      = (const float*)d_in[2];
    const float* qkv_b      = (const float*)d_in[3];
    const float* proj_w     = (const float*)d_in[4];
    const float* proj_b     = (const float*)d_in[5];
    const float* bias_table = (const float*)d_in[6];
    float* out = (float*)d_out;

    const int B = in_sizes[0] / (NTOK * CDIM);   // 8192
    const int smem_bytes = SMEM_FLOATS * (int)sizeof(float);

    prep_all<<<(BM_N + 66048 + 255) / 256, 256>>>(qkv_w, qkv_b, proj_w, proj_b, mask, bias_table);

    cudaFuncSetAttribute(wattn, cudaFuncAttributeMaxDynamicSharedMemorySize, smem_bytes);
    wattn<<<B, THREADS, smem_bytes>>>(x, out);
}

// round 11
// speedup vs baseline: 2.6447x; 2.3801x over previous
#include <cuda_runtime.h>
#include <cuda_fp16.h>
#include <cstdint>

#define NTOK 49
#define CDIM 128
#define NWIN 64
#define THREADS 256

// ---- persistent prepped buffers ----
__device__ __align__(16) __half g_qkvw_h[3 * 128 * 136];  // fp16 [ch][j][136], q-scale folded
__device__ __align__(16) __half g_projw_h[128 * 136];     // fp16 [j][136]
__device__ float g_qkvb[512];                             // fp32 biases (q scaled) ++ proj_b
__device__ float g_bm[64 * 4 * 49 * 56];                  // fused rel-pos bias + mask

// ---- shared memory map (float offsets) ----
#define S_XS 0        // fp16 [64][136] : x tile, later o tile           4352 f
#define S_WB 4352     // fp16 2 x [128][72] weight half-buffers          9216 f
#define S_Q  13568    // fp16 [4][64][40]                                5120 f
#define S_K  18688    // fp16 [4][56][40]                                4480 f
#define S_VT 23168    // fp16 [4][32][56]  (v transposed: [d][token])    3584 f
#define S_SB 26752    // fp32 [512] biases                                512 f
#define SMEMF 27264   // 109056 bytes -> 2 CTAs/SM
// out-stage fp32 [64][132] (8448 f) aliases S_Q..S_K in phase 6

#define XSH 136
#define QSTR 40
#define QHSZ (64 * QSTR)
#define KHSZ (56 * QSTR)
#define VSTR 56
#define VHSZ (32 * VSTR)
#define WBSTR 72

__device__ __forceinline__ uint32_t ldu(const __half* p) {
    return *reinterpret_cast<const uint32_t*>(p);
}
__device__ __forceinline__ void stu(__half* p, uint32_t v) {
    *reinterpret_cast<uint32_t*>(p) = v;
}
__device__ __forceinline__ uint32_t pack2(float a, float b) {
    __half2 h = __floats2half2_rn(a, b);
    return *reinterpret_cast<uint32_t*>(&h);
}

__device__ __forceinline__ void mma16(float c[4], const uint32_t a[4], const uint32_t b[2]) {
    asm volatile(
        "mma.sync.aligned.m16n8k16.row.col.f32.f16.f16.f32 "
        "{%0,%1,%2,%3},{%4,%5,%6,%7},{%8,%9},{%0,%1,%2,%3};\n"
        : "+f"(c[0]), "+f"(c[1]), "+f"(c[2]), "+f"(c[3])
        : "r"(a[0]), "r"(a[1]), "r"(a[2]), "r"(a[3]), "r"(b[0]), "r"(b[1]));
}

__device__ __forceinline__ uint32_t smem_u32(const void* p) {
    return (uint32_t)__cvta_generic_to_shared(p);
}
__device__ __forceinline__ void cp16(uint32_t dst, const void* src) {
    asm volatile("cp.async.cg.shared.global [%0], [%1], 16;\n" :: "r"(dst), "l"(src) : "memory");
}
#define CP_COMMIT asm volatile("cp.async.commit_group;\n" ::: "memory")
#define CP_WAIT0  asm volatile("cp.async.wait_group 0;\n" ::: "memory")
#define CP_WAIT1  asm volatile("cp.async.wait_group 1;\n" ::: "memory")

// stage one 64-col half of a [128][136]h weight matrix into a [128][72]h buffer
__device__ __forceinline__ void stage_half(__half* buf, const __half* gsrc, int hf, int tid) {
#pragma unroll
    for (int i = 0; i < 4; i++) {
        int idx = tid + i * THREADS;         // 0..1023
        int row = idx >> 3, c8 = idx & 7;
        cp16(smem_u32(buf + row * WBSTR + c8 * 8),
             gsrc + row * 136 + hf * 64 + c8 * 8);
    }
}

// ================= merged prep kernel =================
#define BM_N (64 * 4 * 49 * 56)
__global__ void prep_all(const float* __restrict__ qkv_w, const float* __restrict__ qkv_b,
                         const float* __restrict__ proj_w, const float* __restrict__ proj_b,
                         const float* __restrict__ mask, const float* __restrict__ bias_table)
{
    int idx = blockIdx.x * 256 + threadIdx.x;
    const float scale = 0.17677669529663687f;   // 32^-0.5
    if (idx < BM_N) {
        int j = idx % 56;
        int rest = idx / 56;
        int i = rest % 49; rest /= 49;
        int h = rest & 3;
        int w = rest >> 2;
        float v = 0.f;
        if (j < 49) {
            int ih = i / 7, iw = i - 7 * ih;
            int jh = j / 7, jw = j - 7 * jh;
            int ridx = (ih - jh + 6) * 13 + (iw - jw + 6);
            v = bias_table[ridx * 4 + h] + mask[(size_t)(w * 49 + i) * 49 + j];
        }
        g_bm[idx] = v;
        return;
    }
    idx -= BM_N;
    if (idx < 49152) {
        int ch = idx >> 14;
        int j  = (idx >> 7) & 127;
        int k  = idx & 127;
        float v = qkv_w[(size_t)(ch * 128 + j) * 128 + k];
        if (ch == 0) v *= scale;
        g_qkvw_h[ch * 17408 + j * 136 + k] = __float2half_rn(v);
    } else if (idx < 65536) {
        int i2 = idx - 49152;
        int j = i2 >> 7, k = i2 & 127;
        g_projw_h[j * 136 + k] = __float2half_rn(proj_w[(size_t)j * 128 + k]);
    } else if (idx < 65536 + 384) {
        int i = idx - 65536;
        float v = qkv_b[i];
        if (i < 128) v *= scale;
        g_qkvb[i] = v;
    } else if (idx < 65536 + 512) {
        int i = idx - 65536;
        g_qkvb[i] = proj_b[i - 384];
    }
}

// ================= main kernel =================
__global__ __launch_bounds__(THREADS, 2)
void wattn(const float* __restrict__ x, float* __restrict__ out)
{
    extern __shared__ float s[];
    __half* xs  = (__half*)(s + S_XS);
    __half* wb0 = (__half*)(s + S_WB);
    __half* wb1 = (__half*)(s + S_WB + 4608);
    __half* qb  = (__half*)(s + S_Q);
    __half* kb  = (__half*)(s + S_K);
    __half* vt  = (__half*)(s + S_VT);
    float*  sb  = s + S_SB;

    const int tid  = threadIdx.x;
    const int wid  = tid >> 5;
    const int lane = tid & 31;
    const int g    = lane >> 2;
    const int t    = lane & 3;
    const int b    = blockIdx.x;

    // ---- prefetch chunk-0 weights ----
    stage_half(wb0, g_qkvw_h, 0, tid); CP_COMMIT;
    stage_half(wb1, g_qkvw_h, 1, tid); CP_COMMIT;

    // ---- Phase 1: x -> fp16 [64][136], zero-pad rows 49..63; biases ----
    {
        const float4* xb = (const float4*)(x + (size_t)b * (NTOK * CDIM));
#pragma unroll
        for (int it = 0; it < 8; it++) {
            int i = tid + it * THREADS;
            int r = i >> 5, c4 = i & 31;
            float4 v = (r < NTOK) ? xb[r * 32 + c4] : make_float4(0.f, 0.f, 0.f, 0.f);
            stu(xs + r * XSH + c4 * 4,     pack2(v.x, v.y));
            stu(xs + r * XSH + c4 * 4 + 2, pack2(v.z, v.w));
        }
        sb[tid] = g_qkvb[tid];
        sb[tid + 256] = g_qkvb[tid + 256];
    }

    const int m2 = wid & 1;        // 32-row block
    const int nq = wid >> 1;       // 32-col block == head for QKV epilogue
    const int rA = m2 * 32 + g;

    // ---- Phase 2: QKV GEMM, 3 chunks of 128 cols, double-buffered 64-col halves ----
    for (int ch = 0; ch < 3; ch++) {
        CP_WAIT1;
        __syncthreads();

        float acc[2][4][4];
#pragma unroll
        for (int u = 0; u < 2; u++)
#pragma unroll
            for (int i = 0; i < 4; i++)
#pragma unroll
                for (int j = 0; j < 4; j++) acc[u][i][j] = 0.f;

        // half 0: k = 0..63
#pragma unroll
        for (int ks = 0; ks < 4; ks++) {
            const int k0 = ks * 16;
            const __half* ar = xs + rA * XSH + k0 + 2 * t;
            uint32_t a0[4] = { ldu(ar), ldu(ar + 8 * XSH), ldu(ar + 8), ldu(ar + 8 * XSH + 8) };
            const __half* ar2 = ar + 16 * XSH;
            uint32_t a1[4] = { ldu(ar2), ldu(ar2 + 8 * XSH), ldu(ar2 + 8), ldu(ar2 + 8 * XSH + 8) };
#pragma unroll
            for (int nt = 0; nt < 4; nt++) {
                const __half* br = wb0 + (nq * 32 + nt * 8 + g) * WBSTR + k0 + 2 * t;
                uint32_t bb[2] = { ldu(br), ldu(br + 8) };
                mma16(acc[0][nt], a0, bb);
                mma16(acc[1][nt], a1, bb);
            }
        }
        __syncthreads();
        if (ch < 2) { stage_half(wb0, g_qkvw_h + (ch + 1) * 17408, 0, tid); CP_COMMIT; }

        if (ch < 2) { CP_WAIT1; } else { CP_WAIT0; }
        __syncthreads();

        // half 1: k = 64..127
#pragma unroll
        for (int ks = 0; ks < 4; ks++) {
            const int k0 = ks * 16;
            const __half* ar = xs + rA * XSH + 64 + k0 + 2 * t;
            uint32_t a0[4] = { ldu(ar), ldu(ar + 8 * XSH), ldu(ar + 8), ldu(ar + 8 * XSH + 8) };
            const __half* ar2 = ar + 16 * XSH;
            uint32_t a1[4] = { ldu(ar2), ldu(ar2 + 8 * XSH), ldu(ar2 + 8), ldu(ar2 + 8 * XSH + 8) };
#pragma unroll
            for (int nt = 0; nt < 4; nt++) {
                const __half* br = wb1 + (nq * 32 + nt * 8 + g) * WBSTR + k0 + 2 * t;
                uint32_t bb[2] = { ldu(br), ldu(br + 8) };
                mma16(acc[0][nt], a0, bb);
                mma16(acc[1][nt], a1, bb);
            }
        }

        // epilogue -> q / k / vT  (h == nq since cols are 32-aligned)
        {
            const float* bch = sb + ch * 128;
            const int h = nq;
#pragma unroll
            for (int u = 0; u < 2; u++) {
                const int r0 = rA + u * 16;
#pragma unroll
                for (int nt = 0; nt < 4; nt++) {
                    const int c0 = nq * 32 + nt * 8 + 2 * t;
                    const int d0 = nt * 8 + 2 * t;
                    float v0 = acc[u][nt][0] + bch[c0];
                    float v1 = acc[u][nt][1] + bch[c0 + 1];
                    float v2 = acc[u][nt][2] + bch[c0];
                    float v3 = acc[u][nt][3] + bch[c0 + 1];
                    if (ch == 0) {
                        stu(qb + h * QHSZ + r0 * QSTR + d0,       pack2(v0, v1));
                        stu(qb + h * QHSZ + (r0 + 8) * QSTR + d0, pack2(v2, v3));
                    } else if (ch == 1) {
                        if (r0 < 56)     stu(kb + h * KHSZ + r0 * QSTR + d0,       pack2(v0, v1));
                        if (r0 + 8 < 56) stu(kb + h * KHSZ + (r0 + 8) * QSTR + d0, pack2(v2, v3));
                    } else {
                        if (r0 < 56) {
                            vt[h * VHSZ + d0 * VSTR + r0]       = __float2half_rn(v0);
                            vt[h * VHSZ + (d0 + 1) * VSTR + r0] = __float2half_rn(v1);
                        }
                        if (r0 + 8 < 56) {
                            vt[h * VHSZ + d0 * VSTR + r0 + 8]       = __float2half_rn(v2);
                            vt[h * VHSZ + (d0 + 1) * VSTR + r0 + 8] = __float2half_rn(v3);
                        }
                    }
                }
            }
        }
        __syncthreads();
        if (ch < 2) { stage_half(wb1, g_qkvw_h + (ch + 1) * 17408, 1, tid); CP_COMMIT; }
    }

    // ---- prefetch proj weights (wb free now) ----
    stage_half(wb0, g_projw_h, 0, tid); CP_COMMIT;
    stage_half(wb1, g_projw_h, 1, tid); CP_COMMIT;

    // ---- Phases 3+4+5 fused in registers (no barriers) ----
    {
        const int h  = wid >> 1;
        const int mb = wid & 1;                  // 32-row block of this head
        const __half* qh = qb + h * QHSZ;
        const __half* kh = kb + h * KHSZ;
        const __half* vh = vt + h * VHSZ;
        const float* bmw = g_bm + (size_t)(b & (NWIN - 1)) * (4 * 49 * 56) + h * (49 * 56);

#pragma unroll
        for (int u = 0; u < 2; u++) {
            const int r0 = mb * 32 + u * 16 + g;

            // scores: 16x56 via mma, acc[nt][e]
            float acc[7][4];
#pragma unroll
            for (int i = 0; i < 7; i++)
#pragma unroll
                for (int j = 0; j < 4; j++) acc[i][j] = 0.f;

#pragma unroll
            for (int ks = 0; ks < 2; ks++) {
                const int k0 = ks * 16;
                const __half* ar = qh + r0 * QSTR + k0 + 2 * t;
                uint32_t a[4] = { ldu(ar), ldu(ar + 8 * QSTR), ldu(ar + 8), ldu(ar + 8 * QSTR + 8) };
#pragma unroll
                for (int nt = 0; nt < 7; nt++) {
                    const __half* br = kh + (nt * 8 + g) * QSTR + k0 + 2 * t;
                    uint32_t bb[2] = { ldu(br), ldu(br + 8) };
                    mma16(acc[nt], a, bb);
                }
            }

            // + bias+mask (rows clamped to stay in-table; garbage rows discarded later)
            const float* bmA = bmw + (r0 < 49 ? r0 : 0) * 56;
            const float* bmB = bmw + (r0 + 8 < 49 ? r0 + 8 : 0) * 56;
#pragma unroll
            for (int nt = 0; nt < 7; nt++) {
                float2 bA = *(const float2*)(bmA + nt * 8 + 2 * t);
                float2 bB = *(const float2*)(bmB + nt * 8 + 2 * t);
                acc[nt][0] += bA.x; acc[nt][1] += bA.y;
                acc[nt][2] += bB.x; acc[nt][3] += bB.y;
            }
            // mask invalid cols (nt=6: jj = 48+2t+e1, valid only t==0,e1==0)
            if (t > 0) { acc[6][0] = -1e30f; acc[6][2] = -1e30f; }
            acc[6][1] = -1e30f; acc[6][3] = -1e30f;

            // softmax: quad-shuffle reductions
            float mA = -1e30f, mB = -1e30f;
#pragma unroll
            for (int nt = 0; nt < 7; nt++) {
                mA = fmaxf(mA, fmaxf(acc[nt][0], acc[nt][1]));
                mB = fmaxf(mB, fmaxf(acc[nt][2], acc[nt][3]));
            }
            mA = fmaxf(mA, __shfl_xor_sync(0xffffffffu, mA, 1));
            mA = fmaxf(mA, __shfl_xor_sync(0xffffffffu, mA, 2));
            mB = fmaxf(mB, __shfl_xor_sync(0xffffffffu, mB, 1));
            mB = fmaxf(mB, __shfl_xor_sync(0xffffffffu, mB, 2));

            float sA = 0.f, sB = 0.f;
#pragma unroll
            for (int nt = 0; nt < 7; nt++) {
                acc[nt][0] = __expf(acc[nt][0] - mA); sA += acc[nt][0];
                acc[nt][1] = __expf(acc[nt][1] - mA); sA += acc[nt][1];
                acc[nt][2] = __expf(acc[nt][2] - mB); sB += acc[nt][2];
                acc[nt][3] = __expf(acc[nt][3] - mB); sB += acc[nt][3];
            }
            sA += __shfl_xor_sync(0xffffffffu, sA, 1);
            sA += __shfl_xor_sync(0xffffffffu, sA, 2);
            sB += __shfl_xor_sync(0xffffffffu, sB, 1);
            sB += __shfl_xor_sync(0xffffffffu, sB, 2);
            const float invA = 1.0f / sA, invB = 1.0f / sB;

            // pack P into A-fragments (cols 56..63 zero)
            uint32_t pa[4][4];
#pragma unroll
            for (int ks = 0; ks < 4; ks++) {
                const int nt0 = 2 * ks, nt1 = 2 * ks + 1;
                pa[ks][0] = pack2(acc[nt0][0] * invA, acc[nt0][1] * invA);
                pa[ks][1] = pack2(acc[nt0][2] * invB, acc[nt0][3] * invB);
                pa[ks][2] = (nt1 < 7) ? pack2(acc[nt1][0] * invA, acc[nt1][1] * invA) : 0u;
                pa[ks][3] = (nt1 < 7) ? pack2(acc[nt1][2] * invB, acc[nt1][3] * invB) : 0u;
            }

            // o = P @ V  (16x32)
            float o[4][4];
#pragma unroll
            for (int i = 0; i < 4; i++)
#pragma unroll
                for (int j = 0; j < 4; j++) o[i][j] = 0.f;
#pragma unroll
            for (int ks = 0; ks < 4; ks++) {
                const int k0 = ks * 16;
#pragma unroll
                for (int nt = 0; nt < 4; nt++) {
                    const __half* br = vh + (nt * 8 + g) * VSTR + k0 + 2 * t;
                    uint32_t bb[2] = { ldu(br), ldu(br + 8) };
                    mma16(o[nt], pa[ks], bb);
                }
            }

            // write o tile into xs (fp16), cols h*32..
#pragma unroll
            for (int nt = 0; nt < 4; nt++) {
                const int cb = h * 32 + nt * 8 + 2 * t;
                stu(xs + r0 * XSH + cb,       pack2(o[nt][0], o[nt][1]));
                stu(xs + (r0 + 8) * XSH + cb, pack2(o[nt][2], o[nt][3]));
            }
        }
    }

    CP_WAIT0;
    __syncthreads();       // o in xs visible + proj weights staged

    // ---- Phase 6: final = o @ proj_w^T + proj_b ----
    {
        float acc[2][4][4];
#pragma unroll
        for (int u = 0; u < 2; u++)
#pragma unroll
            for (int i = 0; i < 4; i++)
#pragma unroll
                for (int j = 0; j < 4; j++) acc[u][i][j] = 0.f;

#pragma unroll
        for (int hf = 0; hf < 2; hf++) {
            const __half* wb = hf ? wb1 : wb0;
#pragma unroll
            for (int ks = 0; ks < 4; ks++) {
                const int k0 = ks * 16;
                const __half* ar = xs + rA * XSH + hf * 64 + k0 + 2 * t;
                uint32_t a0[4] = { ldu(ar), ldu(ar + 8 * XSH), ldu(ar + 8), ldu(ar + 8 * XSH + 8) };
                const __half* ar2 = ar + 16 * XSH;
                uint32_t a1[4] = { ldu(ar2), ldu(ar2 + 8 * XSH), ldu(ar2 + 8), ldu(ar2 + 8 * XSH + 8) };
#pragma unroll
                for (int nt = 0; nt < 4; nt++) {
                    const __half* br = wb + (nq * 32 + nt * 8 + g) * WBSTR + k0 + 2 * t;
                    uint32_t bb[2] = { ldu(br), ldu(br + 8) };
                    mma16(acc[0][nt], a0, bb);
                    mma16(acc[1][nt], a1, bb);
                }
            }
        }
        __syncthreads();   // everyone done reading xs/wb before out-stage overwrites S_Q

        float* os = s + S_Q;       // fp32 [64][132] over dead q/k region
#pragma unroll
        for (int u = 0; u < 2; u++) {
            const int r0 = rA + u * 16;
#pragma unroll
            for (int nt = 0; nt < 4; nt++) {
                const int c0 = nq * 32 + nt * 8 + 2 * t;
                os[r0 * 132 + c0]           = acc[u][nt][0] + sb[384 + c0];
                os[r0 * 132 + c0 + 1]       = acc[u][nt][1] + sb[384 + c0 + 1];
                os[(r0 + 8) * 132 + c0]     = acc[u][nt][2] + sb[384 + c0];
                os[(r0 + 8) * 132 + c0 + 1] = acc[u][nt][3] + sb[384 + c0 + 1];
            }
        }
    }
    __syncthreads();
    {
        const float* os = s + S_Q;
        float4* ob = (float4*)(out + (size_t)b * (NTOK * CDIM));
        for (int i = tid; i < NTOK * 32; i += THREADS) {
            int r = i >> 5, c4 = i & 31;
            const float* p = os + r * 132 + c4 * 4;
            ob[i] = make_float4(p[0], p[1], p[2], p[3]);
        }
    }
}

extern "C" void kernel_launch(void* const* d_in, const int* in_sizes, int n_in,
                              void* d_out, int out_size)
{
    const float* x          = (const float*)d_in[0];
    const float* mask       = (const float*)d_in[1];
    const float* qkv_w      = (const float*)d_in[2];
    const float* qkv_b      = (const float*)d_in[3];
    const float* proj_w     = (const float*)d_in[4];
    const float* proj_b     = (const float*)d_in[5];
    const float* bias_table = (const float*)d_in[6];
    float* out = (float*)d_out;

    const int B = in_sizes[0] / (NTOK * CDIM);   // 8192
    const int smem_bytes = SMEMF * (int)sizeof(float);

    prep_all<<<(BM_N + 66048 + 255) / 256, 256>>>(qkv_w, qkv_b, proj_w, proj_b, mask, bias_table);

    cudaFuncSetAttribute(wattn, cudaFuncAttributeMaxDynamicSharedMemorySize, smem_bytes);
    wattn<<<B, THREADS, smem_bytes>>>(x, out);
}

// round 12
// speedup vs baseline: 2.8237x; 1.0677x over previous
#include <cuda_runtime.h>
#include <cuda_fp16.h>
#include <cstdint>

#define NTOK 49
#define CDIM 128
#define NWIN 64
#define THREADS 256

// ---- persistent prepped buffers ----
__device__ __align__(16) __half g_qkvw_h[3 * 128 * 136];  // fp16 [ch][j][136], q-scale folded
__device__ __align__(16) __half g_projw_h[128 * 136];     // fp16 [j][136]
__device__ float g_qkvb[512];                             // fp32 biases (q scaled) ++ proj_b
__device__ float g_bm[64 * 4 * 49 * 56];                  // fused rel-pos bias + mask

// ---- shared memory map (float offsets) ----
#define S_XS 0        // fp16 [64][136] : x tile, later o tile           4352 f
#define S_WB 4352     // fp16 2 x [128][72] weight half-buffers          9216 f
#define S_Q  13568    // (q now lives in registers; region used by out-stage)
#define S_K  18688    // fp16 [4][56][40]                                4480 f
#define S_VT 23168    // fp16 [4][32][56]  (v transposed: [d][token])    3584 f
#define S_SB 26752    // fp32 [512] biases                                512 f
#define SMEMF 27264   // 109056 bytes -> 2 CTAs/SM

#define XSH 136
#define QSTR 40
#define KHSZ (56 * QSTR)
#define VSTR 56
#define VHSZ (32 * VSTR)
#define WBSTR 72

__device__ __forceinline__ void stu(__half* p, uint32_t v) {
    *reinterpret_cast<uint32_t*>(p) = v;
}
__device__ __forceinline__ uint32_t pack2(float a, float b) {
    __half2 h = __floats2half2_rn(a, b);
    return *reinterpret_cast<uint32_t*>(&h);
}

__device__ __forceinline__ void mma16(float c[4], const uint32_t a[4],
                                      uint32_t b0, uint32_t b1) {
    asm volatile(
        "mma.sync.aligned.m16n8k16.row.col.f32.f16.f16.f32 "
        "{%0,%1,%2,%3},{%4,%5,%6,%7},{%8,%9},{%0,%1,%2,%3};\n"
        : "+f"(c[0]), "+f"(c[1]), "+f"(c[2]), "+f"(c[3])
        : "r"(a[0]), "r"(a[1]), "r"(a[2]), "r"(a[3]), "r"(b0), "r"(b1));
}

__device__ __forceinline__ uint32_t smem_u32(const void* p) {
    return (uint32_t)__cvta_generic_to_shared(p);
}
__device__ __forceinline__ void ldsm4(uint32_t r[4], uint32_t addr) {
    asm volatile("ldmatrix.sync.aligned.m8n8.x4.shared.b16 {%0,%1,%2,%3}, [%4];"
        : "=r"(r[0]), "=r"(r[1]), "=r"(r[2]), "=r"(r[3]) : "r"(addr));
}
__device__ __forceinline__ void ldsm2(uint32_t r[2], uint32_t addr) {
    asm volatile("ldmatrix.sync.aligned.m8n8.x2.shared.b16 {%0,%1}, [%2];"
        : "=r"(r[0]), "=r"(r[1]) : "r"(addr));
}

__device__ __forceinline__ void cp16(uint32_t dst, const void* src) {
    asm volatile("cp.async.cg.shared.global [%0], [%1], 16;\n" :: "r"(dst), "l"(src) : "memory");
}
#define CP_COMMIT asm volatile("cp.async.commit_group;\n" ::: "memory")
#define CP_WAIT0  asm volatile("cp.async.wait_group 0;\n" ::: "memory")
#define CP_WAIT1  asm volatile("cp.async.wait_group 1;\n" ::: "memory")

__device__ __forceinline__ void stage_half(__half* buf, const __half* gsrc, int hf, int tid) {
#pragma unroll
    for (int i = 0; i < 4; i++) {
        int idx = tid + i * THREADS;         // 0..1023
        int row = idx >> 3, c8 = idx & 7;
        cp16(smem_u32(buf + row * WBSTR + c8 * 8),
             gsrc + row * 136 + hf * 64 + c8 * 8);
    }
}

// ================= merged prep kernel =================
#define BM_N (64 * 4 * 49 * 56)
__global__ void prep_all(const float* __restrict__ qkv_w, const float* __restrict__ qkv_b,
                         const float* __restrict__ proj_w, const float* __restrict__ proj_b,
                         const float* __restrict__ mask, const float* __restrict__ bias_table)
{
    int idx = blockIdx.x * 256 + threadIdx.x;
    const float scale = 0.17677669529663687f;   // 32^-0.5
    if (idx < BM_N) {
        int j = idx % 56;
        int rest = idx / 56;
        int i = rest % 49; rest /= 49;
        int h = rest & 3;
        int w = rest >> 2;
        float v = 0.f;
        if (j < 49) {
            int ih = i / 7, iw = i - 7 * ih;
            int jh = j / 7, jw = j - 7 * jh;
            int ridx = (ih - jh + 6) * 13 + (iw - jw + 6);
            v = bias_table[ridx * 4 + h] + mask[(size_t)(w * 49 + i) * 49 + j];
        }
        g_bm[idx] = v;
        return;
    }
    idx -= BM_N;
    if (idx < 49152) {
        int ch = idx >> 14;
        int j  = (idx >> 7) & 127;
        int k  = idx & 127;
        float v = qkv_w[(size_t)(ch * 128 + j) * 128 + k];
        if (ch == 0) v *= scale;
        g_qkvw_h[ch * 17408 + j * 136 + k] = __float2half_rn(v);
    } else if (idx < 65536) {
        int i2 = idx - 49152;
        int j = i2 >> 7, k = i2 & 127;
        g_projw_h[j * 136 + k] = __float2half_rn(proj_w[(size_t)j * 128 + k]);
    } else if (idx < 65536 + 384) {
        int i = idx - 65536;
        float v = qkv_b[i];
        if (i < 128) v *= scale;
        g_qkvb[i] = v;
    } else if (idx < 65536 + 512) {
        int i = idx - 65536;
        g_qkvb[i] = proj_b[i - 384];
    }
}

// ================= main kernel =================
__global__ __launch_bounds__(THREADS, 2)
void wattn(const float* __restrict__ x, float* __restrict__ out)
{
    extern __shared__ float s[];
    __half* xs  = (__half*)(s + S_XS);
    __half* wb0 = (__half*)(s + S_WB);
    __half* wb1 = (__half*)(s + S_WB + 4608);
    __half* kb  = (__half*)(s + S_K);
    __half* vt  = (__half*)(s + S_VT);
    float*  sb  = s + S_SB;

    const int tid  = threadIdx.x;
    const int wid  = tid >> 5;
    const int lane = tid & 31;
    const int g    = lane >> 2;
    const int t    = lane & 3;
    const int b    = blockIdx.x;

    // ldmatrix lane-role constants
    const int lrA = (lane & 7) + (lane & 8);            // A: row within 16
    const int lkA = (lane & 16) ? 8 : 0;                // A: k-half offset (halfs)
    const int lrB = (lane & 7) + ((lane >> 1) & 8);     // B: row within 16
    const int lkB = lane & 8;                           // B: k-half offset (halfs)

    // ---- prefetch chunk-0 weights ----
    stage_half(wb0, g_qkvw_h, 0, tid); CP_COMMIT;
    stage_half(wb1, g_qkvw_h, 1, tid); CP_COMMIT;

    // ---- Phase 1: x -> fp16 [64][136], zero-pad rows 49..63; biases ----
    {
        const float4* xb = (const float4*)(x + (size_t)b * (NTOK * CDIM));
#pragma unroll
        for (int it = 0; it < 8; it++) {
            int i = tid + it * THREADS;
            int r = i >> 5, c4 = i & 31;
            float4 v = (r < NTOK) ? xb[r * 32 + c4] : make_float4(0.f, 0.f, 0.f, 0.f);
            stu(xs + r * XSH + c4 * 4,     pack2(v.x, v.y));
            stu(xs + r * XSH + c4 * 4 + 2, pack2(v.z, v.w));
        }
        sb[tid] = g_qkvb[tid];
        sb[tid + 256] = g_qkvb[tid + 256];
    }

    const int m2 = wid & 1;        // 32-row block
    const int nq = wid >> 1;       // 32-col block == head
    // LDSM base addresses (bytes)
    const uint32_t aX0 = smem_u32(xs + (m2 * 32 + lrA) * XSH + lkA);
    const uint32_t aX1 = aX0 + 16 * XSH * 2;
    const uint32_t bW0p0 = smem_u32(wb0 + (nq * 32 + lrB) * WBSTR + lkB);
    const uint32_t bW0p1 = bW0p0 + 16 * WBSTR * 2;
    const uint32_t WBOFF = 4608 * 4;   // wb1 - wb0 in bytes

    uint32_t qa[2][2][4];          // q A-fragments, filled at ch==0

    // ---- Phase 2: QKV GEMM, 3 chunks, double-buffered 64-col halves ----
    for (int ch = 0; ch < 3; ch++) {
        CP_WAIT1;
        __syncthreads();

        float acc[2][4][4];
#pragma unroll
        for (int u = 0; u < 2; u++)
#pragma unroll
            for (int i = 0; i < 4; i++)
#pragma unroll
                for (int j = 0; j < 4; j++) acc[u][i][j] = 0.f;

#pragma unroll
        for (int hf = 0; hf < 2; hf++) {
            if (hf == 1) {
                __syncthreads();
                if (ch < 2) { stage_half(wb0, g_qkvw_h + (ch + 1) * 17408, 0, tid); CP_COMMIT; }
                if (ch < 2) { CP_WAIT1; } else { CP_WAIT0; }
                __syncthreads();
            }
            const uint32_t boff = hf ? WBOFF : 0;
#pragma unroll
            for (int ks = 0; ks < 4; ks++) {
                const uint32_t ka = (hf * 64 + ks * 16) * 2;
                uint32_t a0[4], a1[4], q0[4], q1[4];
                ldsm4(a0, aX0 + ka);
                ldsm4(a1, aX1 + ka);
                ldsm4(q0, bW0p0 + boff + ks * 32);
                ldsm4(q1, bW0p1 + boff + ks * 32);
                mma16(acc[0][0], a0, q0[0], q0[1]);
                mma16(acc[1][0], a1, q0[0], q0[1]);
                mma16(acc[0][1], a0, q0[2], q0[3]);
                mma16(acc[1][1], a1, q0[2], q0[3]);
                mma16(acc[0][2], a0, q1[0], q1[1]);
                mma16(acc[1][2], a1, q1[0], q1[1]);
                mma16(acc[0][3], a0, q1[2], q1[3]);
                mma16(acc[1][3], a1, q1[2], q1[3]);
            }
        }

        // epilogue: q -> registers; k, vT -> smem
        {
            const float* bch = sb + ch * 128;
            const int h = nq;
#pragma unroll
            for (int u = 0; u < 2; u++) {
                const int r0 = m2 * 32 + u * 16 + g;
#pragma unroll
                for (int nt = 0; nt < 4; nt++) {
                    const int c0 = nq * 32 + nt * 8 + 2 * t;
                    const int d0 = nt * 8 + 2 * t;
                    float v0 = acc[u][nt][0] + bch[c0];
                    float v1 = acc[u][nt][1] + bch[c0 + 1];
                    float v2 = acc[u][nt][2] + bch[c0];
                    float v3 = acc[u][nt][3] + bch[c0 + 1];
                    if (ch == 0) {
                        qa[u][nt >> 1][(nt & 1) * 2]     = pack2(v0, v1);
                        qa[u][nt >> 1][(nt & 1) * 2 + 1] = pack2(v2, v3);
                    } else if (ch == 1) {
                        if (r0 < 56)     stu(kb + h * KHSZ + r0 * QSTR + d0,       pack2(v0, v1));
                        if (r0 + 8 < 56) stu(kb + h * KHSZ + (r0 + 8) * QSTR + d0, pack2(v2, v3));
                    } else {
                        if (r0 < 56) {
                            vt[h * VHSZ + d0 * VSTR + r0]       = __float2half_rn(v0);
                            vt[h * VHSZ + (d0 + 1) * VSTR + r0] = __float2half_rn(v1);
                        }
                        if (r0 + 8 < 56) {
                            vt[h * VHSZ + d0 * VSTR + r0 + 8]       = __float2half_rn(v2);
                            vt[h * VHSZ + (d0 + 1) * VSTR + r0 + 8] = __float2half_rn(v3);
                        }
                    }
                }
            }
        }
        __syncthreads();
        if (ch < 2) { stage_half(wb1, g_qkvw_h + (ch + 1) * 17408, 1, tid); CP_COMMIT; }
    }

    // ---- prefetch proj weights ----
    stage_half(wb0, g_projw_h, 0, tid); CP_COMMIT;
    stage_half(wb1, g_projw_h, 1, tid); CP_COMMIT;

    // ---- Phases 3+4+5 fused in registers ----
    {
        const int h = nq;          // == wid>>1
        const __half* kh = kb + h * KHSZ;
        const __half* vh = vt + h * VHSZ;
        const float* bmw = g_bm + (size_t)(b & (NWIN - 1)) * (4 * 49 * 56) + h * (49 * 56);

        const uint32_t bK = smem_u32(kh + lrB * QSTR + lkB);
        const uint32_t bK2 = smem_u32(kh + (48 + (lane & 7)) * QSTR + (lane & 8));
        const uint32_t bV = smem_u32(vh + lrB * VSTR + lkB);

#pragma unroll
        for (int u = 0; u < 2; u++) {
            const int r0 = m2 * 32 + u * 16 + g;

            float acc[7][4];
#pragma unroll
            for (int i = 0; i < 7; i++)
#pragma unroll
                for (int j = 0; j < 4; j++) acc[i][j] = 0.f;

#pragma unroll
            for (int ks = 0; ks < 2; ks++) {
                const uint32_t ka = ks * 32;
                uint32_t k01[4], k23[4], k45[4], k6[2];
                ldsm4(k01, bK + ka);
                ldsm4(k23, bK + 16 * QSTR * 2 + ka);
                ldsm4(k45, bK + 32 * QSTR * 2 + ka);
                ldsm2(k6,  bK2 + ka);
                mma16(acc[0], qa[u][ks], k01[0], k01[1]);
                mma16(acc[1], qa[u][ks], k01[2], k01[3]);
                mma16(acc[2], qa[u][ks], k23[0], k23[1]);
                mma16(acc[3], qa[u][ks], k23[2], k23[3]);
                mma16(acc[4], qa[u][ks], k45[0], k45[1]);
                mma16(acc[5], qa[u][ks], k45[2], k45[3]);
                mma16(acc[6], qa[u][ks], k6[0],  k6[1]);
            }

            // + bias+mask (rows clamped; garbage rows discarded downstream)
            const float* bmA = bmw + (r0 < 49 ? r0 : 0) * 56;
            const float* bmB = bmw + (r0 + 8 < 49 ? r0 + 8 : 0) * 56;
#pragma unroll
            for (int nt = 0; nt < 7; nt++) {
                float2 bA = *(const float2*)(bmA + nt * 8 + 2 * t);
                float2 bB = *(const float2*)(bmB + nt * 8 + 2 * t);
                acc[nt][0] += bA.x; acc[nt][1] += bA.y;
                acc[nt][2] += bB.x; acc[nt][3] += bB.y;
            }
            if (t > 0) { acc[6][0] = -1e30f; acc[6][2] = -1e30f; }
            acc[6][1] = -1e30f; acc[6][3] = -1e30f;

            // softmax via quad shuffles
            float mA = -1e30f, mB = -1e30f;
#pragma unroll
            for (int nt = 0; nt < 7; nt++) {
                mA = fmaxf(mA, fmaxf(acc[nt][0], acc[nt][1]));
                mB = fmaxf(mB, fmaxf(acc[nt][2], acc[nt][3]));
            }
            mA = fmaxf(mA, __shfl_xor_sync(0xffffffffu, mA, 1));
            mA = fmaxf(mA, __shfl_xor_sync(0xffffffffu, mA, 2));
            mB = fmaxf(mB, __shfl_xor_sync(0xffffffffu, mB, 1));
            mB = fmaxf(mB, __shfl_xor_sync(0xffffffffu, mB, 2));

            float sA = 0.f, sB = 0.f;
#pragma unroll
            for (int nt = 0; nt < 7; nt++) {
                acc[nt][0] = __expf(acc[nt][0] - mA); sA += acc[nt][0];
                acc[nt][1] = __expf(acc[nt][1] - mA); sA += acc[nt][1];
                acc[nt][2] = __expf(acc[nt][2] - mB); sB += acc[nt][2];
                acc[nt][3] = __expf(acc[nt][3] - mB); sB += acc[nt][3];
            }
            sA += __shfl_xor_sync(0xffffffffu, sA, 1);
            sA += __shfl_xor_sync(0xffffffffu, sA, 2);
            sB += __shfl_xor_sync(0xffffffffu, sB, 1);
            sB += __shfl_xor_sync(0xffffffffu, sB, 2);
            const float invA = 1.0f / sA, invB = 1.0f / sB;

            // P -> A-fragments
            uint32_t pa[4][4];
#pragma unroll
            for (int ks = 0; ks < 4; ks++) {
                const int nt0 = 2 * ks, nt1 = 2 * ks + 1;
                pa[ks][0] = pack2(acc[nt0][0] * invA, acc[nt0][1] * invA);
                pa[ks][1] = pack2(acc[nt0][2] * invB, acc[nt0][3] * invB);
                pa[ks][2] = (nt1 < 7) ? pack2(acc[nt1][0] * invA, acc[nt1][1] * invA) : 0u;
                pa[ks][3] = (nt1 < 7) ? pack2(acc[nt1][2] * invB, acc[nt1][3] * invB) : 0u;
            }

            // o = P @ V
            float o[4][4];
#pragma unroll
            for (int i = 0; i < 4; i++)
#pragma unroll
                for (int j = 0; j < 4; j++) o[i][j] = 0.f;
#pragma unroll
            for (int ks = 0; ks < 4; ks++) {
                uint32_t v01[4], v23[4];
                ldsm4(v01, bV + ks * 32);
                ldsm4(v23, bV + 16 * VSTR * 2 + ks * 32);
                mma16(o[0], pa[ks], v01[0], v01[1]);
                mma16(o[1], pa[ks], v01[2], v01[3]);
                mma16(o[2], pa[ks], v23[0], v23[1]);
                mma16(o[3], pa[ks], v23[2], v23[3]);
            }

            // o tile -> xs (fp16), cols h*32..
#pragma unroll
            for (int nt = 0; nt < 4; nt++) {
                const int cb = h * 32 + nt * 8 + 2 * t;
                stu(xs + r0 * XSH + cb,       pack2(o[nt][0], o[nt][1]));
                stu(xs + (r0 + 8) * XSH + cb, pack2(o[nt][2], o[nt][3]));
            }
        }
    }

    CP_WAIT0;
    __syncthreads();       // o visible + proj weights staged

    // ---- Phase 6: final = o @ proj_w^T + proj_b ----
    {
        float acc[2][4][4];
#pragma unroll
        for (int u = 0; u < 2; u++)
#pragma unroll
            for (int i = 0; i < 4; i++)
#pragma unroll
                for (int j = 0; j < 4; j++) acc[u][i][j] = 0.f;

#pragma unroll
        for (int hf = 0; hf < 2; hf++) {
            const uint32_t boff = hf ? WBOFF : 0;
#pragma unroll
            for (int ks = 0; ks < 4; ks++) {
                const uint32_t ka = (hf * 64 + ks * 16) * 2;
                uint32_t a0[4], a1[4], q0[4], q1[4];
                ldsm4(a0, aX0 + ka);
                ldsm4(a1, aX1 + ka);
                ldsm4(q0, bW0p0 + boff + ks * 32);
                ldsm4(q1, bW0p1 + boff + ks * 32);
                mma16(acc[0][0], a0, q0[0], q0[1]);
                mma16(acc[1][0], a1, q0[0], q0[1]);
                mma16(acc[0][1], a0, q0[2], q0[3]);
                mma16(acc[1][1], a1, q0[2], q0[3]);
                mma16(acc[0][2], a0, q1[0], q1[1]);
                mma16(acc[1][2], a1, q1[0], q1[1]);
                mma16(acc[0][3], a0, q1[2], q1[3]);
                mma16(acc[1][3], a1, q1[2], q1[3]);
            }
        }
        __syncthreads();   // done reading xs/wb before out-stage overwrite

        float* os = s + S_Q;       // fp32 [64][132]
#pragma unroll
        for (int u = 0; u < 2; u++) {
            const int r0 = m2 * 32 + u * 16 + g;
#pragma unroll
            for (int nt = 0; nt < 4; nt++) {
                const int c0 = nq * 32 + nt * 8 + 2 * t;
                os[r0 * 132 + c0]           = acc[u][nt][0] + sb[384 + c0];
                os[r0 * 132 + c0 + 1]       = acc[u][nt][1] + sb[384 + c0 + 1];
                os[(r0 + 8) * 132 + c0]     = acc[u][nt][2] + sb[384 + c0];
                os[(r0 + 8) * 132 + c0 + 1] = acc[u][nt][3] + sb[384 + c0 + 1];
            }
        }
    }
    __syncthreads();
    {
        const float* os = s + S_Q;
        float4* ob = (float4*)(out + (size_t)b * (NTOK * CDIM));
        for (int i = tid; i < NTOK * 32; i += THREADS) {
            int r = i >> 5, c4 = i & 31;
            const float* p = os + r * 132 + c4 * 4;
            ob[i] = make_float4(p[0], p[1], p[2], p[3]);
        }
    }
}

extern "C" void kernel_launch(void* const* d_in, const int* in_sizes, int n_in,
                              void* d_out, int out_size)
{
    const float* x          = (const float*)d_in[0];
    const float* mask       = (const float*)d_in[1];
    const float* qkv_w      = (const float*)d_in[2];
    const float* qkv_b      = (const float*)d_in[3];
    const float* proj_w     = (const float*)d_in[4];
    const float* proj_b     = (const float*)d_in[5];
    const float* bias_table = (const float*)d_in[6];
    float* out = (float*)d_out;

    const int B = in_sizes[0] / (NTOK * CDIM);   // 8192
    const int smem_bytes = SMEMF * (int)sizeof(float);

    prep_all<<<(BM_N + 66048 + 255) / 256, 256>>>(qkv_w, qkv_b, proj_w, proj_b, mask, bias_table);

    cudaFuncSetAttribute(wattn, cudaFuncAttributeMaxDynamicSharedMemorySize, smem_bytes);
    wattn<<<B, THREADS, smem_bytes>>>(x, out);
}

// round 13
// speedup vs baseline: 2.9173x; 1.0331x over previous
#include <cuda_runtime.h>
#include <cuda_fp16.h>
#include <cstdint>

#define NTOK 49
#define CDIM 128
#define NWIN 64
#define THREADS 256

// ---- persistent prepped buffers ----
__device__ __align__(16) __half g_qkvw_h[3 * 128 * 136];  // fp16 [ch][j][136], q-scale folded
__device__ __align__(16) __half g_projw_h[128 * 136];     // fp16 [j][136]
__device__ float g_qkvb[512];                             // fp32 biases (q scaled) ++ proj_b
__device__ float g_bm[64 * 4 * 49 * 56];                  // fused rel-pos bias + mask

// ---- shared memory map (float offsets) ----
#define S_XS 0        // fp16 [64][136] : x tile, later o tile           4352 f
#define S_WB 4352     // fp16 2 x [128][72] weight half-buffers          9216 f
#define S_Q  13568    // out-stage region (q lives in registers)
#define S_K  18688    // fp16 [4][56][40]                                4480 f
#define S_VT 23168    // fp16 [4][32][56]  (v transposed: [d][token])    3584 f
#define S_SB 26752    // fp32 [512] biases                                512 f
#define SMEMF 27264   // 109056 bytes -> 2 CTAs/SM

#define XSH 136
#define QSTR 40
#define KHSZ (56 * QSTR)
#define VSTR 56
#define VHSZ (32 * VSTR)
#define WBSTR 72

__device__ __forceinline__ void stu(__half* p, uint32_t v) {
    *reinterpret_cast<uint32_t*>(p) = v;
}
__device__ __forceinline__ uint32_t pack2(float a, float b) {
    __half2 h = __floats2half2_rn(a, b);
    return *reinterpret_cast<uint32_t*>(&h);
}

__device__ __forceinline__ void mma16(float c[4], const uint32_t a[4],
                                      uint32_t b0, uint32_t b1) {
    asm volatile(
        "mma.sync.aligned.m16n8k16.row.col.f32.f16.f16.f32 "
        "{%0,%1,%2,%3},{%4,%5,%6,%7},{%8,%9},{%0,%1,%2,%3};\n"
        : "+f"(c[0]), "+f"(c[1]), "+f"(c[2]), "+f"(c[3])
        : "r"(a[0]), "r"(a[1]), "r"(a[2]), "r"(a[3]), "r"(b0), "r"(b1));
}

__device__ __forceinline__ uint32_t smem_u32(const void* p) {
    return (uint32_t)__cvta_generic_to_shared(p);
}
__device__ __forceinline__ void ldsm4(uint32_t r[4], uint32_t addr) {
    asm volatile("ldmatrix.sync.aligned.m8n8.x4.shared.b16 {%0,%1,%2,%3}, [%4];"
        : "=r"(r[0]), "=r"(r[1]), "=r"(r[2]), "=r"(r[3]) : "r"(addr));
}
__device__ __forceinline__ void ldsm2(uint32_t r[2], uint32_t addr) {
    asm volatile("ldmatrix.sync.aligned.m8n8.x2.shared.b16 {%0,%1}, [%2];"
        : "=r"(r[0]), "=r"(r[1]) : "r"(addr));
}

__device__ __forceinline__ void cp16(uint32_t dst, const void* src) {
    asm volatile("cp.async.cg.shared.global [%0], [%1], 16;\n" :: "r"(dst), "l"(src) : "memory");
}
#define CP_COMMIT asm volatile("cp.async.commit_group;\n" ::: "memory")
#define CP_WAIT0  asm volatile("cp.async.wait_group 0;\n" ::: "memory")
#define CP_WAIT1  asm volatile("cp.async.wait_group 1;\n" ::: "memory")

__device__ __forceinline__ void stage_half(__half* buf, const __half* gsrc, int hf, int tid) {
#pragma unroll
    for (int i = 0; i < 4; i++) {
        int idx = tid + i * THREADS;         // 0..1023
        int row = idx >> 3, c8 = idx & 7;
        cp16(smem_u32(buf + row * WBSTR + c8 * 8),
             gsrc + row * 136 + hf * 64 + c8 * 8);
    }
}

// ================= merged prep kernel =================
#define BM_N (64 * 4 * 49 * 56)
__global__ void prep_all(const float* __restrict__ qkv_w, const float* __restrict__ qkv_b,
                         const float* __restrict__ proj_w, const float* __restrict__ proj_b,
                         const float* __restrict__ mask, const float* __restrict__ bias_table)
{
    int idx = blockIdx.x * 256 + threadIdx.x;
    const float scale = 0.17677669529663687f;   // 32^-0.5
    if (idx < BM_N) {
        int j = idx % 56;
        int rest = idx / 56;
        int i = rest % 49; rest /= 49;
        int h = rest & 3;
        int w = rest >> 2;
        float v = 0.f;
        if (j < 49) {
            int ih = i / 7, iw = i - 7 * ih;
            int jh = j / 7, jw = j - 7 * jh;
            int ridx = (ih - jh + 6) * 13 + (iw - jw + 6);
            v = bias_table[ridx * 4 + h] + mask[(size_t)(w * 49 + i) * 49 + j];
        }
        g_bm[idx] = v;
        return;
    }
    idx -= BM_N;
    if (idx < 49152) {
        int ch = idx >> 14;
        int j  = (idx >> 7) & 127;
        int k  = idx & 127;
        float v = qkv_w[(size_t)(ch * 128 + j) * 128 + k];
        if (ch == 0) v *= scale;
        g_qkvw_h[ch * 17408 + j * 136 + k] = __float2half_rn(v);
    } else if (idx < 65536) {
        int i2 = idx - 49152;
        int j = i2 >> 7, k = i2 & 127;
        g_projw_h[j * 136 + k] = __float2half_rn(proj_w[(size_t)j * 128 + k]);
    } else if (idx < 65536 + 384) {
        int i = idx - 65536;
        float v = qkv_b[i];
        if (i < 128) v *= scale;
        g_qkvb[i] = v;
    } else if (idx < 65536 + 512) {
        int i = idx - 65536;
        g_qkvb[i] = proj_b[i - 384];
    }
}

// ================= main kernel =================
__global__ __launch_bounds__(THREADS, 2)
void wattn(const float* __restrict__ x, float* __restrict__ out)
{
    extern __shared__ float s[];
    __half* xs  = (__half*)(s + S_XS);
    __half* wb0 = (__half*)(s + S_WB);
    __half* wb1 = (__half*)(s + S_WB + 4608);
    __half* kb  = (__half*)(s + S_K);
    __half* vt  = (__half*)(s + S_VT);
    float*  sb  = s + S_SB;

    const int tid  = threadIdx.x;
    const int wid  = tid >> 5;
    const int lane = tid & 31;
    const int g    = lane >> 2;
    const int t    = lane & 3;
    const int b    = blockIdx.x;

    // ldmatrix lane-role constants
    const int lrA = (lane & 7) + (lane & 8);            // A: row within 16
    const int lkA = (lane & 16) ? 8 : 0;                // A: k-half offset (halfs)
    const int lrB = (lane & 7) + ((lane >> 1) & 8);     // B: row within 16
    const int lkB = lane & 8;                           // B: k-half offset (halfs)

    // ---- prefetch chunk-0 weights ----
    stage_half(wb0, g_qkvw_h, 0, tid); CP_COMMIT;
    stage_half(wb1, g_qkvw_h, 1, tid); CP_COMMIT;

    // ---- Phase 1: x -> fp16 [64][136] via 128-bit STS; zero-pad rows; biases ----
    {
        const float4* xb = (const float4*)(x + (size_t)b * (NTOK * CDIM));
#pragma unroll
        for (int it = 0; it < 4; it++) {
            int i = tid + it * THREADS;        // 0..1023
            int r = i >> 4, c16 = i & 15;      // 16-byte column unit (8 halfs)
            float4 v0, v1;
            if (r < NTOK) { v0 = xb[r * 32 + c16 * 2]; v1 = xb[r * 32 + c16 * 2 + 1]; }
            else { v0 = make_float4(0.f,0.f,0.f,0.f); v1 = v0; }
            uint32_t p0 = pack2(v0.x, v0.y), p1 = pack2(v0.z, v0.w);
            uint32_t p2 = pack2(v1.x, v1.y), p3 = pack2(v1.z, v1.w);
            asm volatile("st.shared.v4.b32 [%0], {%1,%2,%3,%4};"
                :: "r"(smem_u32(xs + r * XSH + c16 * 8)),
                   "r"(p0), "r"(p1), "r"(p2), "r"(p3) : "memory");
        }
        sb[tid] = g_qkvb[tid];
        sb[tid + 256] = g_qkvb[tid + 256];
    }

    const int m2 = wid & 1;        // 32-row block
    const int nq = wid >> 1;       // 32-col block == head
    // LDSM base addresses (bytes)
    const uint32_t aX0 = smem_u32(xs + (m2 * 32 + lrA) * XSH + lkA);
    const uint32_t aX1 = aX0 + 16 * XSH * 2;
    const uint32_t bW0p0 = smem_u32(wb0 + (nq * 32 + lrB) * WBSTR + lkB);
    const uint32_t bW0p1 = bW0p0 + 16 * WBSTR * 2;
    const uint32_t WBOFF = 4608 * 4;   // wb1 - wb0 in bytes

    uint32_t qa[2][2][4];          // q A-fragments, filled at ch==0

    // ---- Phase 2: QKV GEMM, 3 chunks, double-buffered 64-col halves ----
    for (int ch = 0; ch < 3; ch++) {
        CP_WAIT1;
        __syncthreads();

        float acc[2][4][4];
#pragma unroll
        for (int u = 0; u < 2; u++)
#pragma unroll
            for (int i = 0; i < 4; i++)
#pragma unroll
                for (int j = 0; j < 4; j++) acc[u][i][j] = 0.f;

#pragma unroll
        for (int hf = 0; hf < 2; hf++) {
            if (hf == 1) {
                __syncthreads();
                if (ch < 2) { stage_half(wb0, g_qkvw_h + (ch + 1) * 17408, 0, tid); CP_COMMIT; }
                if (ch < 2) { CP_WAIT1; } else { CP_WAIT0; }
                __syncthreads();
            }
            const uint32_t boff = hf ? WBOFF : 0;
#pragma unroll
            for (int ks = 0; ks < 4; ks++) {
                const uint32_t ka = (hf * 64 + ks * 16) * 2;
                uint32_t a0[4], a1[4], q0[4], q1[4];
                ldsm4(a0, aX0 + ka);
                ldsm4(a1, aX1 + ka);
                ldsm4(q0, bW0p0 + boff + ks * 32);
                ldsm4(q1, bW0p1 + boff + ks * 32);
                mma16(acc[0][0], a0, q0[0], q0[1]);
                mma16(acc[1][0], a1, q0[0], q0[1]);
                mma16(acc[0][1], a0, q0[2], q0[3]);
                mma16(acc[1][1], a1, q0[2], q0[3]);
                mma16(acc[0][2], a0, q1[0], q1[1]);
                mma16(acc[1][2], a1, q1[0], q1[1]);
                mma16(acc[0][3], a0, q1[2], q1[3]);
                mma16(acc[1][3], a1, q1[2], q1[3]);
            }
        }

        // epilogue: q -> registers; k, vT -> smem
        {
            const float* bch = sb + ch * 128;
            const int h = nq;
#pragma unroll
            for (int u = 0; u < 2; u++) {
                const int r0 = m2 * 32 + u * 16 + g;
#pragma unroll
                for (int nt = 0; nt < 4; nt++) {
                    const int c0 = nq * 32 + nt * 8 + 2 * t;
                    const int d0 = nt * 8 + 2 * t;
                    float v0 = acc[u][nt][0] + bch[c0];
                    float v1 = acc[u][nt][1] + bch[c0 + 1];
                    float v2 = acc[u][nt][2] + bch[c0];
                    float v3 = acc[u][nt][3] + bch[c0 + 1];
                    if (ch == 0) {
                        qa[u][nt >> 1][(nt & 1) * 2]     = pack2(v0, v1);
                        qa[u][nt >> 1][(nt & 1) * 2 + 1] = pack2(v2, v3);
                    } else if (ch == 1) {
                        if (r0 < 56)     stu(kb + h * KHSZ + r0 * QSTR + d0,       pack2(v0, v1));
                        if (r0 + 8 < 56) stu(kb + h * KHSZ + (r0 + 8) * QSTR + d0, pack2(v2, v3));
                    } else {
                        if (r0 < 56) {
                            vt[h * VHSZ + d0 * VSTR + r0]       = __float2half_rn(v0);
                            vt[h * VHSZ + (d0 + 1) * VSTR + r0] = __float2half_rn(v1);
                        }
                        if (r0 + 8 < 56) {
                            vt[h * VHSZ + d0 * VSTR + r0 + 8]       = __float2half_rn(v2);
                            vt[h * VHSZ + (d0 + 1) * VSTR + r0 + 8] = __float2half_rn(v3);
                        }
                    }
                }
            }
        }
        __syncthreads();
        if (ch < 2) { stage_half(wb1, g_qkvw_h + (ch + 1) * 17408, 1, tid); CP_COMMIT; }
    }

    // ---- prefetch proj weights ----
    stage_half(wb0, g_projw_h, 0, tid); CP_COMMIT;
    stage_half(wb1, g_projw_h, 1, tid); CP_COMMIT;

    // ---- Phases 3+4+5 fused, u-inner (K/V fragments loaded once) ----
    {
        const int h = nq;
        const __half* kh = kb + h * KHSZ;
        const __half* vh = vt + h * VHSZ;
        const float* bmw = g_bm + (size_t)(b & (NWIN - 1)) * (4 * 49 * 56) + h * (49 * 56);

        const uint32_t bK  = smem_u32(kh + lrB * QSTR + lkB);
        const uint32_t bK2 = smem_u32(kh + (48 + (lane & 7)) * QSTR + (lane & 8));
        const uint32_t bV  = smem_u32(vh + lrB * VSTR + lkB);

        // scores for BOTH u tiles against one K-fragment stream
        float acc[2][7][4];
#pragma unroll
        for (int u = 0; u < 2; u++)
#pragma unroll
            for (int i = 0; i < 7; i++)
#pragma unroll
                for (int j = 0; j < 4; j++) acc[u][i][j] = 0.f;

#pragma unroll
        for (int ks = 0; ks < 2; ks++) {
            const uint32_t ka = ks * 32;
            uint32_t k01[4], k23[4], k45[4], k6[2];
            ldsm4(k01, bK + ka);
            ldsm4(k23, bK + 16 * QSTR * 2 + ka);
            ldsm4(k45, bK + 32 * QSTR * 2 + ka);
            ldsm2(k6,  bK2 + ka);
#pragma unroll
            for (int u = 0; u < 2; u++) {
                mma16(acc[u][0], qa[u][ks], k01[0], k01[1]);
                mma16(acc[u][1], qa[u][ks], k01[2], k01[3]);
                mma16(acc[u][2], qa[u][ks], k23[0], k23[1]);
                mma16(acc[u][3], qa[u][ks], k23[2], k23[3]);
                mma16(acc[u][4], qa[u][ks], k45[0], k45[1]);
                mma16(acc[u][5], qa[u][ks], k45[2], k45[3]);
                mma16(acc[u][6], qa[u][ks], k6[0],  k6[1]);
            }
        }

        // bias+mask, masking, softmax, P packing — per u (independent chains)
        uint32_t pa[2][4][4];
#pragma unroll
        for (int u = 0; u < 2; u++) {
            const int r0 = m2 * 32 + u * 16 + g;
            const float* bmA = bmw + (r0 < 49 ? r0 : 0) * 56;
            const float* bmB = bmw + (r0 + 8 < 49 ? r0 + 8 : 0) * 56;
#pragma unroll
            for (int nt = 0; nt < 7; nt++) {
                float2 bA = *(const float2*)(bmA + nt * 8 + 2 * t);
                float2 bB = *(const float2*)(bmB + nt * 8 + 2 * t);
                acc[u][nt][0] += bA.x; acc[u][nt][1] += bA.y;
                acc[u][nt][2] += bB.x; acc[u][nt][3] += bB.y;
            }
            if (t > 0) { acc[u][6][0] = -1e30f; acc[u][6][2] = -1e30f; }
            acc[u][6][1] = -1e30f; acc[u][6][3] = -1e30f;

            float mA = -1e30f, mB = -1e30f;
#pragma unroll
            for (int nt = 0; nt < 7; nt++) {
                mA = fmaxf(mA, fmaxf(acc[u][nt][0], acc[u][nt][1]));
                mB = fmaxf(mB, fmaxf(acc[u][nt][2], acc[u][nt][3]));
            }
            mA = fmaxf(mA, __shfl_xor_sync(0xffffffffu, mA, 1));
            mA = fmaxf(mA, __shfl_xor_sync(0xffffffffu, mA, 2));
            mB = fmaxf(mB, __shfl_xor_sync(0xffffffffu, mB, 1));
            mB = fmaxf(mB, __shfl_xor_sync(0xffffffffu, mB, 2));

            float sA = 0.f, sB = 0.f;
#pragma unroll
            for (int nt = 0; nt < 7; nt++) {
                acc[u][nt][0] = __expf(acc[u][nt][0] - mA); sA += acc[u][nt][0];
                acc[u][nt][1] = __expf(acc[u][nt][1] - mA); sA += acc[u][nt][1];
                acc[u][nt][2] = __expf(acc[u][nt][2] - mB); sB += acc[u][nt][2];
                acc[u][nt][3] = __expf(acc[u][nt][3] - mB); sB += acc[u][nt][3];
            }
            sA += __shfl_xor_sync(0xffffffffu, sA, 1);
            sA += __shfl_xor_sync(0xffffffffu, sA, 2);
            sB += __shfl_xor_sync(0xffffffffu, sB, 1);
            sB += __shfl_xor_sync(0xffffffffu, sB, 2);
            const float invA = 1.0f / sA, invB = 1.0f / sB;

#pragma unroll
            for (int ks = 0; ks < 4; ks++) {
                const int nt0 = 2 * ks, nt1 = 2 * ks + 1;
                pa[u][ks][0] = pack2(acc[u][nt0][0] * invA, acc[u][nt0][1] * invA);
                pa[u][ks][1] = pack2(acc[u][nt0][2] * invB, acc[u][nt0][3] * invB);
                pa[u][ks][2] = (nt1 < 7) ? pack2(acc[u][nt1][0] * invA, acc[u][nt1][1] * invA) : 0u;
                pa[u][ks][3] = (nt1 < 7) ? pack2(acc[u][nt1][2] * invB, acc[u][nt1][3] * invB) : 0u;
            }
        }

        // o = P @ V for BOTH u tiles against one V-fragment stream
        float o[2][4][4];
#pragma unroll
        for (int u = 0; u < 2; u++)
#pragma unroll
            for (int i = 0; i < 4; i++)
#pragma unroll
                for (int j = 0; j < 4; j++) o[u][i][j] = 0.f;

#pragma unroll
        for (int ks = 0; ks < 4; ks++) {
            uint32_t v01[4], v23[4];
            ldsm4(v01, bV + ks * 32);
            ldsm4(v23, bV + 16 * VSTR * 2 + ks * 32);
#pragma unroll
            for (int u = 0; u < 2; u++) {
                mma16(o[u][0], pa[u][ks], v01[0], v01[1]);
                mma16(o[u][1], pa[u][ks], v01[2], v01[3]);
                mma16(o[u][2], pa[u][ks], v23[0], v23[1]);
                mma16(o[u][3], pa[u][ks], v23[2], v23[3]);
            }
        }

        // o tiles -> xs (fp16), cols h*32..
#pragma unroll
        for (int u = 0; u < 2; u++) {
            const int r0 = m2 * 32 + u * 16 + g;
#pragma unroll
            for (int nt = 0; nt < 4; nt++) {
                const int cb = h * 32 + nt * 8 + 2 * t;
                stu(xs + r0 * XSH + cb,       pack2(o[u][nt][0], o[u][nt][1]));
                stu(xs + (r0 + 8) * XSH + cb, pack2(o[u][nt][2], o[u][nt][3]));
            }
        }
    }

    CP_WAIT0;
    __syncthreads();       // o visible + proj weights staged

    // ---- Phase 6: final = o @ proj_w^T + proj_b ----
    {
        float acc[2][4][4];
#pragma unroll
        for (int u = 0; u < 2; u++)
#pragma unroll
            for (int i = 0; i < 4; i++)
#pragma unroll
                for (int j = 0; j < 4; j++) acc[u][i][j] = 0.f;

#pragma unroll
        for (int hf = 0; hf < 2; hf++) {
            const uint32_t boff = hf ? WBOFF : 0;
#pragma unroll
            for (int ks = 0; ks < 4; ks++) {
                const uint32_t ka = (hf * 64 + ks * 16) * 2;
                uint32_t a0[4], a1[4], q0[4], q1[4];
                ldsm4(a0, aX0 + ka);
                ldsm4(a1, aX1 + ka);
                ldsm4(q0, bW0p0 + boff + ks * 32);
                ldsm4(q1, bW0p1 + boff + ks * 32);
                mma16(acc[0][0], a0, q0[0], q0[1]);
                mma16(acc[1][0], a1, q0[0], q0[1]);
                mma16(acc[0][1], a0, q0[2], q0[3]);
                mma16(acc[1][1], a1, q0[2], q0[3]);
                mma16(acc[0][2], a0, q1[0], q1[1]);
                mma16(acc[1][2], a1, q1[0], q1[1]);
                mma16(acc[0][3], a0, q1[2], q1[3]);
                mma16(acc[1][3], a1, q1[2], q1[3]);
            }
        }
        __syncthreads();   // done reading xs/wb before out-stage overwrite

        float* os = s + S_Q;       // fp32 [64][132]
#pragma unroll
        for (int u = 0; u < 2; u++) {
            const int r0 = m2 * 32 + u * 16 + g;
#pragma unroll
            for (int nt = 0; nt < 4; nt++) {
                const int c0 = nq * 32 + nt * 8 + 2 * t;
                float2 w0 = make_float2(acc[u][nt][0] + sb[384 + c0],
                                        acc[u][nt][1] + sb[384 + c0 + 1]);
                float2 w1 = make_float2(acc[u][nt][2] + sb[384 + c0],
                                        acc[u][nt][3] + sb[384 + c0 + 1]);
                *(float2*)(os + r0 * 132 + c0)       = w0;
                *(float2*)(os + (r0 + 8) * 132 + c0) = w1;
            }
        }
    }
    __syncthreads();
    {
        const float* os = s + S_Q;
        float4* ob = (float4*)(out + (size_t)b * (NTOK * CDIM));
        for (int i = tid; i < NTOK * 32; i += THREADS) {
            int r = i >> 5, c4 = i & 31;
            const float* p = os + r * 132 + c4 * 4;
            ob[i] = make_float4(p[0], p[1], p[2], p[3]);
        }
    }
}

extern "C" void kernel_launch(void* const* d_in, const int* in_sizes, int n_in,
                              void* d_out, int out_size)
{
    const float* x          = (const float*)d_in[0];
    const float* mask       = (const float*)d_in[1];
    const float* qkv_w      = (const float*)d_in[2];
    const float* qkv_b      = (const float*)d_in[3];
    const float* proj_w     = (const float*)d_in[4];
    const float* proj_b     = (const float*)d_in[5];
    const float* bias_table = (const float*)d_in[6];
    float* out = (float*)d_out;

    const int B = in_sizes[0] / (NTOK * CDIM);   // 8192
    const int smem_bytes = SMEMF * (int)sizeof(float);

    prep_all<<<(BM_N + 66048 + 255) / 256, 256>>>(qkv_w, qkv_b, proj_w, proj_b, mask, bias_table);

    cudaFuncSetAttribute(wattn, cudaFuncAttributeMaxDynamicSharedMemorySize, smem_bytes);
    wattn<<<B, THREADS, smem_bytes>>>(x, out);
}

// round 16
// speedup vs baseline: 3.0102x; 1.0319x over previous
#include <cuda_runtime.h>
#include <cuda_fp16.h>
#include <cstdint>

#define NTOK 49
#define CDIM 128
#define THREADS 512

// ---- persistent prepped buffers ----
__device__ __align__(16) __half g_wall[4 * 128 * 136];   // fp16 [ch][j][136]: qkv0,1,2,proj; q-scale folded
__device__ float g_qkvb[512];                            // fp32 biases (q scaled) ++ proj_b
__device__ float g_bm[64 * 4 * 49 * 56];                 // fused rel-pos bias + mask

// ---- smem byte map (1 CTA/SM, persistent) ----
#define O_W   0        // 4 x [128][136]h weights = 139264
#define O_XS  139264   // [64][136]h x/o tile     = 17408
#define O_K   156672   // [4][56][40]h            = 17920
#define O_V   174592   // [4][32][72]h vT (padded)= 18432
#define O_SCR 193024   // [49][128]f32 raw x      = 25088
#define O_SB  218112   // 512 f32 biases          = 2048
#define SMEM_BYTES 220160

#define WSTR 136       // halfs
#define CHH  17408     // halfs per weight chunk
#define QSTR 40
#define KHSZ (56 * QSTR)
#define VSTR 72        // padded: tokens 56..71 are ZERO (set once in prologue)
#define VHSZ (32 * VSTR)

__device__ __forceinline__ void stu(__half* p, uint32_t v) {
    *reinterpret_cast<uint32_t*>(p) = v;
}
__device__ __forceinline__ uint32_t pack2(float a, float b) {
    __half2 h = __floats2half2_rn(a, b);
    return *reinterpret_cast<uint32_t*>(&h);
}
__device__ __forceinline__ void mma16(float c[4], const uint32_t a[4],
                                      uint32_t b0, uint32_t b1) {
    asm volatile(
        "mma.sync.aligned.m16n8k16.row.col.f32.f16.f16.f32 "
        "{%0,%1,%2,%3},{%4,%5,%6,%7},{%8,%9},{%0,%1,%2,%3};\n"
        : "+f"(c[0]), "+f"(c[1]), "+f"(c[2]), "+f"(c[3])
        : "r"(a[0]), "r"(a[1]), "r"(a[2]), "r"(a[3]), "r"(b0), "r"(b1));
}
__device__ __forceinline__ uint32_t smem_u32(const void* p) {
    return (uint32_t)__cvta_generic_to_shared(p);
}
__device__ __forceinline__ void ldsm4(uint32_t r[4], uint32_t addr) {
    asm volatile("ldmatrix.sync.aligned.m8n8.x4.shared.b16 {%0,%1,%2,%3}, [%4];"
        : "=r"(r[0]), "=r"(r[1]), "=r"(r[2]), "=r"(r[3]) : "r"(addr));
}
__device__ __forceinline__ void ldsm2(uint32_t r[2], uint32_t addr) {
    asm volatile("ldmatrix.sync.aligned.m8n8.x2.shared.b16 {%0,%1}, [%2];"
        : "=r"(r[0]), "=r"(r[1]) : "r"(addr));
}
__device__ __forceinline__ void cp16(uint32_t dst, const void* src) {
    asm volatile("cp.async.cg.shared.global [%0], [%1], 16;\n" :: "r"(dst), "l"(src) : "memory");
}
#define CP_COMMIT asm volatile("cp.async.commit_group;\n" ::: "memory")
#define CP_WAIT0  asm volatile("cp.async.wait_group 0;\n" ::: "memory")

// ================= merged prep kernel =================
#define BM_N (64 * 4 * 49 * 56)
__global__ void prep_all(const float* __restrict__ qkv_w, const float* __restrict__ qkv_b,
                         const float* __restrict__ proj_w, const float* __restrict__ proj_b,
                         const float* __restrict__ mask, const float* __restrict__ bias_table)
{
    int idx = blockIdx.x * 256 + threadIdx.x;
    const float scale = 0.17677669529663687f;   // 32^-0.5
    if (idx < BM_N) {
        int j = idx % 56;
        int rest = idx / 56;
        int i = rest % 49; rest /= 49;
        int h = rest & 3;
        int w = rest >> 2;
        float v = 0.f;
        if (j < 49) {
            int ih = i / 7, iw = i - 7 * ih;
            int jh = j / 7, jw = j - 7 * jh;
            int ridx = (ih - jh + 6) * 13 + (iw - jw + 6);
            v = bias_table[ridx * 4 + h] + mask[(size_t)(w * 49 + i) * 49 + j];
        }
        g_bm[idx] = v;
        return;
    }
    idx -= BM_N;
    if (idx < 49152) {
        int ch = idx >> 14;
        int j  = (idx >> 7) & 127;
        int k  = idx & 127;
        float v = qkv_w[(size_t)(ch * 128 + j) * 128 + k];
        if (ch == 0) v *= scale;
        g_wall[ch * CHH + j * WSTR + k] = __float2half_rn(v);
    } else if (idx < 65536) {
        int i2 = idx - 49152;
        int j = i2 >> 7, k = i2 & 127;
        g_wall[3 * CHH + j * WSTR + k] = __float2half_rn(proj_w[(size_t)j * 128 + k]);
    } else if (idx < 65536 + 384) {
        int i = idx - 65536;
        float v = qkv_b[i];
        if (i < 128) v *= scale;
        g_qkvb[i] = v;
    } else if (idx < 65536 + 512) {
        int i = idx - 65536;
        g_qkvb[i] = proj_b[i - 384];
    }
}

// ================= persistent main kernel =================
__global__ __launch_bounds__(THREADS, 1)
void wattn(const float* __restrict__ x, float* __restrict__ out, int NW)
{
    extern __shared__ char smem[];
    __half* ws  = (__half*)(smem + O_W);
    __half* xs  = (__half*)(smem + O_XS);
    __half* kb  = (__half*)(smem + O_K);
    __half* vt  = (__half*)(smem + O_V);
    float*  scr = (float*)(smem + O_SCR);
    float*  sb  = (float*)(smem + O_SB);

    const int tid  = threadIdx.x;
    const int wid  = tid >> 5;
    const int lane = tid & 31;
    const int g    = lane >> 2;
    const int t    = lane & 3;

    const int lrA = (lane & 7) + (lane & 8);
    const int lkA = (lane & 16) ? 8 : 0;
    const int lrB = (lane & 7) + ((lane >> 1) & 8);
    const int lkB = lane & 8;

    const uint32_t sm32 = smem_u32(smem);

    // ---- prologue: stage ALL weights once; first x; zero vt; biases ----
#pragma unroll
    for (int i = 0; i < 17; i++) {
        int idx = tid + i * THREADS;          // 0..8703 (x16B = 139264 B)
        cp16(sm32 + O_W + idx * 16, (const char*)g_wall + idx * 16);
    }
    {
        const char* xsrc = (const char*)(x + (size_t)blockIdx.x * (NTOK * CDIM));
#pragma unroll
        for (int i = 0; i < 4; i++) {
            int idx = tid + i * THREADS;
            if (idx < 1568) cp16(sm32 + O_SCR + idx * 16, xsrc + idx * 16);
        }
    }
    CP_COMMIT;
    // zero vt region ONCE (padding tokens 56..71 stay zero forever; Phase B
    // only ever writes tokens 0..55)
    {
        uint4 z = make_uint4(0, 0, 0, 0);
#pragma unroll
        for (int i = 0; i < 3; i++) {
            int idx = tid + i * THREADS;      // 0..1151 (x16B = 18432 B)
            if (idx < 1152)
                asm volatile("st.shared.v4.b32 [%0], {%1,%2,%3,%4};"
                    :: "r"(sm32 + O_V + idx * 16), "r"(z.x), "r"(z.y), "r"(z.z), "r"(z.w)
                    : "memory");
        }
    }
    sb[tid] = g_qkvb[tid];

    const int mi = wid & 3;       // 16-row block
    const int nq = wid >> 2;      // 32-col block == head
    const uint32_t aX  = smem_u32(xs + (mi * 16 + lrA) * WSTR + lkA);
    const uint32_t bW  = smem_u32(ws + (nq * 32 + lrB) * WSTR + lkB);
    const int r0 = mi * 16 + g;

    for (int w = blockIdx.x; w < NW; w += gridDim.x) {
        CP_WAIT0;
        __syncthreads();

        // ---- Phase A: scratch fp32 -> xs fp16 [64][136], pad rows 49..63 ----
#pragma unroll
        for (int it = 0; it < 4; it++) {
            int i = tid + it * THREADS;       // 0..2047
            int r = i >> 5, c4 = i & 31;
            float4 v = (r < NTOK) ? ((const float4*)scr)[i]
                                  : make_float4(0.f, 0.f, 0.f, 0.f);
            stu(xs + r * WSTR + c4 * 4,     pack2(v.x, v.y));
            stu(xs + r * WSTR + c4 * 4 + 2, pack2(v.z, v.w));
        }
        // prefetch next window's x (per-thread idx ownership == phase-A reads)
        {
            int wn = w + gridDim.x;
            if (wn < NW) {
                const char* xsrc = (const char*)(x + (size_t)wn * (NTOK * CDIM));
#pragma unroll
                for (int i2 = 0; i2 < 4; i2++) {
                    int idx = tid + i2 * THREADS;
                    if (idx < 1568) cp16(sm32 + O_SCR + idx * 16, xsrc + idx * 16);
                }
            }
            CP_COMMIT;
        }
        __syncthreads();

        // ---- Phase B: QKV (3 chunks, resident weights, no inner barriers) ----
        uint32_t qa[2][4];
#pragma unroll
        for (int ch = 0; ch < 3; ch++) {
            float acc[4][4];
#pragma unroll
            for (int i = 0; i < 4; i++)
#pragma unroll
                for (int j = 0; j < 4; j++) acc[i][j] = 0.f;

            const uint32_t bC0 = bW + ch * (CHH * 2);
            const uint32_t bC1 = bC0 + 16 * WSTR * 2;
#pragma unroll
            for (int ks = 0; ks < 8; ks++) {
                uint32_t a0[4], q0[4], q1[4];
                ldsm4(a0, aX + ks * 32);
                ldsm4(q0, bC0 + ks * 32);
                ldsm4(q1, bC1 + ks * 32);
                mma16(acc[0], a0, q0[0], q0[1]);
                mma16(acc[1], a0, q0[2], q0[3]);
                mma16(acc[2], a0, q1[0], q1[1]);
                mma16(acc[3], a0, q1[2], q1[3]);
            }

            const float* bch = sb + ch * 128;
#pragma unroll
            for (int nt = 0; nt < 4; nt++) {
                const int c0 = nq * 32 + nt * 8 + 2 * t;
                const int d0 = nt * 8 + 2 * t;
                float v0 = acc[nt][0] + bch[c0];
                float v1 = acc[nt][1] + bch[c0 + 1];
                float v2 = acc[nt][2] + bch[c0];
                float v3 = acc[nt][3] + bch[c0 + 1];
                if (ch == 0) {
                    qa[nt >> 1][(nt & 1) * 2]     = pack2(v0, v1);
                    qa[nt >> 1][(nt & 1) * 2 + 1] = pack2(v2, v3);
                } else if (ch == 1) {
                    stu(kb + nq * KHSZ + r0 * QSTR + d0, pack2(v0, v1));
                    if (r0 + 8 < 56)
                        stu(kb + nq * KHSZ + (r0 + 8) * QSTR + d0, pack2(v2, v3));
                } else {
                    __half* vd = vt + nq * VHSZ;
                    vd[d0 * VSTR + r0]       = __float2half_rn(v0);
                    vd[(d0 + 1) * VSTR + r0] = __float2half_rn(v1);
                    if (r0 + 8 < 56) {
                        vd[d0 * VSTR + r0 + 8]       = __float2half_rn(v2);
                        vd[(d0 + 1) * VSTR + r0 + 8] = __float2half_rn(v3);
                    }
                }
            }
        }
        __syncthreads();

        // ---- Phase C: fused attention (warp = head nq, rows mi*16..+15) ----
        {
            const int h = nq;
            const __half* kh = kb + h * KHSZ;
            const __half* vh = vt + h * VHSZ;
            const float* bmw = g_bm + (size_t)(w & 63) * (4 * 49 * 56) + h * (49 * 56);

            const uint32_t bK  = smem_u32(kh + lrB * QSTR + lkB);
            const uint32_t bK2 = smem_u32(kh + (48 + (lane & 7)) * QSTR + (lane & 8));
            const uint32_t bV  = smem_u32(vh + lrB * VSTR + lkB);

            float acc[7][4];
#pragma unroll
            for (int i = 0; i < 7; i++)
#pragma unroll
                for (int j = 0; j < 4; j++) acc[i][j] = 0.f;

#pragma unroll
            for (int ks = 0; ks < 2; ks++) {
                const uint32_t ka = ks * 32;
                uint32_t k01[4], k23[4], k45[4], k6[2];
                ldsm4(k01, bK + ka);
                ldsm4(k23, bK + 16 * QSTR * 2 + ka);
                ldsm4(k45, bK + 32 * QSTR * 2 + ka);
                ldsm2(k6,  bK2 + ka);
                mma16(acc[0], qa[ks], k01[0], k01[1]);
                mma16(acc[1], qa[ks], k01[2], k01[3]);
                mma16(acc[2], qa[ks], k23[0], k23[1]);
                mma16(acc[3], qa[ks], k23[2], k23[3]);
                mma16(acc[4], qa[ks], k45[0], k45[1]);
                mma16(acc[5], qa[ks], k45[2], k45[3]);
                mma16(acc[6], qa[ks], k6[0],  k6[1]);
            }

            const float* bmA = bmw + (r0 < 49 ? r0 : 0) * 56;
            const float* bmB = bmw + (r0 + 8 < 49 ? r0 + 8 : 0) * 56;
#pragma unroll
            for (int nt = 0; nt < 7; nt++) {
                float2 bA = *(const float2*)(bmA + nt * 8 + 2 * t);
                float2 bB = *(const float2*)(bmB + nt * 8 + 2 * t);
                acc[nt][0] += bA.x; acc[nt][1] += bA.y;
                acc[nt][2] += bB.x; acc[nt][3] += bB.y;
            }
            if (t > 0) { acc[6][0] = -1e30f; acc[6][2] = -1e30f; }
            acc[6][1] = -1e30f; acc[6][3] = -1e30f;

            float mA = -1e30f, mB = -1e30f;
#pragma unroll
            for (int nt = 0; nt < 7; nt++) {
                mA = fmaxf(mA, fmaxf(acc[nt][0], acc[nt][1]));
                mB = fmaxf(mB, fmaxf(acc[nt][2], acc[nt][3]));
            }
            mA = fmaxf(mA, __shfl_xor_sync(0xffffffffu, mA, 1));
            mA = fmaxf(mA, __shfl_xor_sync(0xffffffffu, mA, 2));
            mB = fmaxf(mB, __shfl_xor_sync(0xffffffffu, mB, 1));
            mB = fmaxf(mB, __shfl_xor_sync(0xffffffffu, mB, 2));

            float sA = 0.f, sB = 0.f;
#pragma unroll
            for (int nt = 0; nt < 7; nt++) {
                acc[nt][0] = __expf(acc[nt][0] - mA); sA += acc[nt][0];
                acc[nt][1] = __expf(acc[nt][1] - mA); sA += acc[nt][1];
                acc[nt][2] = __expf(acc[nt][2] - mB); sB += acc[nt][2];
                acc[nt][3] = __expf(acc[nt][3] - mB); sB += acc[nt][3];
            }
            sA += __shfl_xor_sync(0xffffffffu, sA, 1);
            sA += __shfl_xor_sync(0xffffffffu, sA, 2);
            sB += __shfl_xor_sync(0xffffffffu, sB, 1);
            sB += __shfl_xor_sync(0xffffffffu, sB, 2);
            const float invA = 1.0f / sA, invB = 1.0f / sB;

            uint32_t pa[4][4];
#pragma unroll
            for (int ks = 0; ks < 4; ks++) {
                const int nt0 = 2 * ks, nt1 = 2 * ks + 1;
                pa[ks][0] = pack2(acc[nt0][0] * invA, acc[nt0][1] * invA);
                pa[ks][1] = pack2(acc[nt0][2] * invB, acc[nt0][3] * invB);
                pa[ks][2] = (nt1 < 7) ? pack2(acc[nt1][0] * invA, acc[nt1][1] * invA) : 0u;
                pa[ks][3] = (nt1 < 7) ? pack2(acc[nt1][2] * invB, acc[nt1][3] * invB) : 0u;
            }

            float o[4][4];
#pragma unroll
            for (int i = 0; i < 4; i++)
#pragma unroll
                for (int j = 0; j < 4; j++) o[i][j] = 0.f;
#pragma unroll
            for (int ks = 0; ks < 4; ks++) {
                uint32_t v01[4], v23[4];
                ldsm4(v01, bV + ks * 32);
                ldsm4(v23, bV + 16 * VSTR * 2 + ks * 32);
                mma16(o[0], pa[ks], v01[0], v01[1]);
                mma16(o[1], pa[ks], v01[2], v01[3]);
                mma16(o[2], pa[ks], v23[0], v23[1]);
                mma16(o[3], pa[ks], v23[2], v23[3]);
            }

#pragma unroll
            for (int nt = 0; nt < 4; nt++) {
                const int cb = h * 32 + nt * 8 + 2 * t;
                stu(xs + r0 * WSTR + cb,       pack2(o[nt][0], o[nt][1]));
                stu(xs + (r0 + 8) * WSTR + cb, pack2(o[nt][2], o[nt][3]));
            }
        }
        __syncthreads();

        // ---- Phase D: proj GEMM + direct global store ----
        {
            float acc[4][4];
#pragma unroll
            for (int i = 0; i < 4; i++)
#pragma unroll
                for (int j = 0; j < 4; j++) acc[i][j] = 0.f;

            const uint32_t bC0 = bW + 3 * (CHH * 2);
            const uint32_t bC1 = bC0 + 16 * WSTR * 2;
#pragma unroll
            for (int ks = 0; ks < 8; ks++) {
                uint32_t a0[4], q0[4], q1[4];
                ldsm4(a0, aX + ks * 32);
                ldsm4(q0, bC0 + ks * 32);
                ldsm4(q1, bC1 + ks * 32);
                mma16(acc[0], a0, q0[0], q0[1]);
                mma16(acc[1], a0, q0[2], q0[3]);
                mma16(acc[2], a0, q1[0], q1[1]);
                mma16(acc[3], a0, q1[2], q1[3]);
            }

            float* op = out + (size_t)w * (NTOK * CDIM);
#pragma unroll
            for (int nt = 0; nt < 4; nt++) {
                const int c0 = nq * 32 + nt * 8 + 2 * t;
                if (r0 < NTOK) {
                    float2 v = make_float2(acc[nt][0] + sb[384 + c0],
                                           acc[nt][1] + sb[384 + c0 + 1]);
                    *(float2*)(op + r0 * CDIM + c0) = v;
                }
                if (r0 + 8 < NTOK) {
                    float2 v = make_float2(acc[nt][2] + sb[384 + c0],
                                           acc[nt][3] + sb[384 + c0 + 1]);
                    *(float2*)(op + (r0 + 8) * CDIM + c0) = v;
                }
            }
        }
        // loop-top __syncthreads protects xs/kb/vt reuse
    }
}

extern "C" void kernel_launch(void* const* d_in, const int* in_sizes, int n_in,
                              void* d_out, int out_size)
{
    const float* x          = (const float*)d_in[0];
    const float* mask       = (const float*)d_in[1];
    const float* qkv_w      = (const float*)d_in[2];
    const float* qkv_b      = (const float*)d_in[3];
    const float* proj_w     = (const float*)d_in[4];
    const float* proj_b     = (const float*)d_in[5];
    const float* bias_table = (const float*)d_in[6];
    float* out = (float*)d_out;

    const int NW = in_sizes[0] / (NTOK * CDIM);   // 8192 windows

    prep_all<<<(BM_N + 66048 + 255) / 256, 256>>>(qkv_w, qkv_b, proj_w, proj_b, mask, bias_table);

    int sms = 0;
    cudaDeviceGetAttribute(&sms, cudaDevAttrMultiProcessorCount, 0);
    if (sms <= 0) sms = 148;
    int grid = (sms < NW) ? sms : NW;

    cudaFuncSetAttribute(wattn, cudaFuncAttributeMaxDynamicSharedMemorySize, SMEM_BYTES);
    wattn<<<grid, THREADS, SMEM_BYTES>>>(x, out, NW);
}